// round 1
// baseline (speedup 1.0000x reference)
#include <cuda_runtime.h>
#include <math.h>

#define BSZ 2
#define QLEN 1024
#define MLEN 1024
#define KLEN 2048
#define NH 16
#define DH 64
#define DM 1024

// ---------------- scratch (device globals; no allocation allowed) ----------------
__device__ float g_kin[BSZ*KLEN*DM];   // concat(mem, x)      16MB
__device__ float g_q  [BSZ*QLEN*DM];   // q proj               8MB
__device__ float g_k  [BSZ*KLEN*DM];   // k proj              16MB
__device__ float g_v  [BSZ*KLEN*DM];   // v proj              16MB
__device__ float g_r  [KLEN*DM];       // r proj               8MB
__device__ float g_av [BSZ*QLEN*DM];   // attention output     8MB

// ---------------- concat kernel: g_kin[b] = [mem[b]; x[b]] ----------------
__global__ void concat_kernel(const float* __restrict__ mem, const float* __restrict__ x) {
    int idx = blockIdx.x * blockDim.x + threadIdx.x;          // float4 index
    const int total = BSZ*KLEN*DM/4;
    if (idx >= total) return;
    int e4   = idx & (DM/4 - 1);
    int rest = idx / (DM/4);
    int j = rest & (KLEN - 1);
    int b = rest >> 11;
    float4 v;
    if (j < MLEN) v = reinterpret_cast<const float4*>(mem)[(b*MLEN + j)*(DM/4) + e4];
    else          v = reinterpret_cast<const float4*>(x)[(b*QLEN + (j - MLEN))*(DM/4) + e4];
    reinterpret_cast<float4*>(g_kin)[idx] = v;
}

// ---------------- NT GEMM: C[M,N] = A[M,K] * B[N,K]^T ----------------
// 128x128 tile, BK=8, 256 threads, 8x8 micro-tile per thread.
__global__ __launch_bounds__(256, 2) void gemm_nt(
    const float* __restrict__ A, const float* __restrict__ Bm, float* __restrict__ C,
    int M, int N, int K)
{
    __shared__ float As[8][132];
    __shared__ float Bs[8][132];
    const int tid = threadIdx.x;
    const int tx = tid & 15, ty = tid >> 4;
    const int m0 = blockIdx.y * 128, n0 = blockIdx.x * 128;
    const int lm = tid >> 1;
    const int lk = (tid & 1) * 4;
    const float* Arow = A + (m0 + lm) * K + lk;
    const float* Brow = Bm + (n0 + lm) * K + lk;

    float acc[8][8];
    #pragma unroll
    for (int i = 0; i < 8; i++)
        #pragma unroll
        for (int j = 0; j < 8; j++) acc[i][j] = 0.f;

    for (int k0 = 0; k0 < K; k0 += 8) {
        float4 av = *reinterpret_cast<const float4*>(Arow + k0);
        float4 bv = *reinterpret_cast<const float4*>(Brow + k0);
        As[lk+0][lm] = av.x; As[lk+1][lm] = av.y; As[lk+2][lm] = av.z; As[lk+3][lm] = av.w;
        Bs[lk+0][lm] = bv.x; Bs[lk+1][lm] = bv.y; Bs[lk+2][lm] = bv.z; Bs[lk+3][lm] = bv.w;
        __syncthreads();
        #pragma unroll
        for (int kk = 0; kk < 8; kk++) {
            float4 a0 = *reinterpret_cast<const float4*>(&As[kk][ty*4]);
            float4 a1 = *reinterpret_cast<const float4*>(&As[kk][64 + ty*4]);
            float4 b0 = *reinterpret_cast<const float4*>(&Bs[kk][tx*4]);
            float4 b1 = *reinterpret_cast<const float4*>(&Bs[kk][64 + tx*4]);
            float a[8] = {a0.x,a0.y,a0.z,a0.w,a1.x,a1.y,a1.z,a1.w};
            float b[8] = {b0.x,b0.y,b0.z,b0.w,b1.x,b1.y,b1.z,b1.w};
            #pragma unroll
            for (int i = 0; i < 8; i++)
                #pragma unroll
                for (int j = 0; j < 8; j++)
                    acc[i][j] = fmaf(a[i], b[j], acc[i][j]);
        }
        __syncthreads();
    }
    #pragma unroll
    for (int i = 0; i < 8; i++) {
        int row = m0 + ((i < 4) ? (ty*4 + i) : (64 + ty*4 + i - 4));
        float4 v0 = make_float4(acc[i][0], acc[i][1], acc[i][2], acc[i][3]);
        float4 v1 = make_float4(acc[i][4], acc[i][5], acc[i][6], acc[i][7]);
        *reinterpret_cast<float4*>(&C[row*N + n0 + tx*4])      = v0;
        *reinterpret_cast<float4*>(&C[row*N + n0 + 64 + tx*4]) = v1;
    }
}

// ---------------- fused relative attention (flash style) ----------------
// Grid: (QLEN/64, BSZ*NH). 256 threads. Per block: 64 q rows of one head.
// Score(i,j) = [ (q_i+u)·k_j + (q_i+v)·r_{j+QLEN-1-i} ] / 8, masked j > i+MLEN.
#define QU_S 68     // padded stride for d-major 64x64 tiles
#define RT_S 128    // r band stride (t dimension)
#define SM_QU 0
#define SM_QV 4352
#define SM_KT 8704   // k tile, reused as P^T after scores
#define SM_VS 13056
#define SM_RT 17152
#define SM_TOTF (17152 + 64*RT_S)   // 25344 floats = 101376 bytes

__global__ __launch_bounds__(256, 2) void attn_kernel(
    const float* __restrict__ r_w_bias, const float* __restrict__ r_r_bias)
{
    extern __shared__ float smemf[];
    float* quT = smemf + SM_QU;   // [d][i]  (q + r_w_bias)
    float* qvT = smemf + SM_QV;   // [d][i]  (q + r_r_bias)
    float* kT  = smemf + SM_KT;   // [d][j]  -> reused as Pt[j][i]
    float* vs  = smemf + SM_VS;   // [j][dh]
    float* rT  = smemf + SM_RT;   // [d][t]  r band

    const int tid = threadIdx.x;
    const int tx = tid & 15, ty = tid >> 4;
    const int i0 = blockIdx.x * 64;
    const int bn = blockIdx.y;
    const int b = bn >> 4, n = bn & 15;

    // ---- load q tile, add both biases, store d-major ----
    {
        int ii = tid >> 2, c = tid & 3;
        const float* qrow = g_q + (b*QLEN + i0 + ii)*DM + n*DH;
        const float4* ub = reinterpret_cast<const float4*>(r_w_bias + n*DH);
        const float4* vb = reinterpret_cast<const float4*>(r_r_bias + n*DH);
        #pragma unroll
        for (int r = 0; r < 4; r++) {
            int d4 = c + r*4;
            float4 q4 = reinterpret_cast<const float4*>(qrow)[d4];
            float4 u4 = ub[d4];
            float4 v4 = vb[d4];
            quT[(d4*4+0)*QU_S + ii] = q4.x + u4.x;
            quT[(d4*4+1)*QU_S + ii] = q4.y + u4.y;
            quT[(d4*4+2)*QU_S + ii] = q4.z + u4.z;
            quT[(d4*4+3)*QU_S + ii] = q4.w + u4.w;
            qvT[(d4*4+0)*QU_S + ii] = q4.x + v4.x;
            qvT[(d4*4+1)*QU_S + ii] = q4.y + v4.y;
            qvT[(d4*4+2)*QU_S + ii] = q4.z + v4.z;
            qvT[(d4*4+3)*QU_S + ii] = q4.w + v4.w;
        }
    }

    float out[4][4];
    #pragma unroll
    for (int i = 0; i < 4; i++)
        #pragma unroll
        for (int j = 0; j < 4; j++) out[i][j] = 0.f;
    float lsum[4] = {0.f, 0.f, 0.f, 0.f};
    float mrun[4] = {-1e30f, -1e30f, -1e30f, -1e30f};

    const int ntiles = i0/64 + 17;            // last tile: j0 = i0 + MLEN
    const int rbase = 4*(tx - ty + 15);       // band base for this thread's micro-tile

    for (int kt = 0; kt < ntiles; kt++) {
        const int j0 = kt * 64;
        __syncthreads();   // previous-iteration consumers of kT/vs/rT done (also covers quT init)

        // ---- load k tile (d-major) and v tile (row-major) ----
        {
            int jj = tid >> 2, c = tid & 3;
            const float* krow = g_k + (b*KLEN + j0 + jj)*DM + n*DH;
            const float* vrow = g_v + (b*KLEN + j0 + jj)*DM + n*DH;
            #pragma unroll
            for (int r = 0; r < 4; r++) {
                int d4 = c + r*4;
                float4 k4 = reinterpret_cast<const float4*>(krow)[d4];
                kT[(d4*4+0)*QU_S + jj] = k4.x;
                kT[(d4*4+1)*QU_S + jj] = k4.y;
                kT[(d4*4+2)*QU_S + jj] = k4.z;
                kT[(d4*4+3)*QU_S + jj] = k4.w;
                float4 v4 = reinterpret_cast<const float4*>(vrow)[d4];
                *reinterpret_cast<float4*>(&vs[jj*64 + d4*4]) = v4;
            }
        }
        // ---- load r band: rel = j + 1023 - i covers [rel_lo, rel_lo+126] ----
        {
            int t = tid >> 1, c = tid & 1;
            int rel = (j0 - i0 + 960) + t;
            rel = rel < 0 ? 0 : (rel > KLEN-1 ? KLEN-1 : rel);  // clamped rows are masked anyway
            const float* rrow = g_r + rel*DM + n*DH;
            #pragma unroll
            for (int r8 = 0; r8 < 8; r8++) {
                int d4 = c*8 + r8;
                float4 r4 = reinterpret_cast<const float4*>(rrow)[d4];
                rT[(d4*4+0)*RT_S + t] = r4.x;
                rT[(d4*4+1)*RT_S + t] = r4.y;
                rT[(d4*4+2)*RT_S + t] = r4.z;
                rT[(d4*4+3)*RT_S + t] = r4.w;
            }
        }
        __syncthreads();

        // ---- scores: AC + banded BD ----
        float ac[4][4], bd[4][4];
        #pragma unroll
        for (int i = 0; i < 4; i++)
            #pragma unroll
            for (int j = 0; j < 4; j++) { ac[i][j] = 0.f; bd[i][j] = 0.f; }

        #pragma unroll 4
        for (int d = 0; d < DH; d++) {
            float4 a4 = *reinterpret_cast<const float4*>(&quT[d*QU_S + ty*4]);
            float4 k4 = *reinterpret_cast<const float4*>(&kT [d*QU_S + tx*4]);
            float4 c4 = *reinterpret_cast<const float4*>(&qvT[d*QU_S + ty*4]);
            float4 r0 = *reinterpret_cast<const float4*>(&rT [d*RT_S + rbase]);
            float4 r1 = *reinterpret_cast<const float4*>(&rT [d*RT_S + rbase + 4]);
            float av[4] = {a4.x, a4.y, a4.z, a4.w};
            float kv[4] = {k4.x, k4.y, k4.z, k4.w};
            float cv[4] = {c4.x, c4.y, c4.z, c4.w};
            float rv[8] = {r0.x, r0.y, r0.z, r0.w, r1.x, r1.y, r1.z, r1.w};
            #pragma unroll
            for (int iy = 0; iy < 4; iy++)
                #pragma unroll
                for (int jx = 0; jx < 4; jx++) {
                    ac[iy][jx] = fmaf(av[iy], kv[jx], ac[iy][jx]);
                    bd[iy][jx] = fmaf(cv[iy], rv[jx - iy + 3], bd[iy][jx]);
                }
        }

        // ---- combine, mask, online softmax (reuse ac as s/p storage) ----
        #pragma unroll
        for (int iy = 0; iy < 4; iy++) {
            int ii = i0 + ty*4 + iy;
            #pragma unroll
            for (int jx = 0; jx < 4; jx++) {
                float s = (ac[iy][jx] + bd[iy][jx]) * 0.125f;
                if (j0 + tx*4 + jx > ii + MLEN) s = -1e30f;
                ac[iy][jx] = s;
            }
        }
        float mnew[4], rsum[4];
        #pragma unroll
        for (int iy = 0; iy < 4; iy++) {
            float tm = fmaxf(fmaxf(ac[iy][0], ac[iy][1]), fmaxf(ac[iy][2], ac[iy][3]));
            #pragma unroll
            for (int off = 8; off > 0; off >>= 1)
                tm = fmaxf(tm, __shfl_xor_sync(0xffffffffu, tm, off));
            mnew[iy] = fmaxf(mrun[iy], tm);
            float rs = 0.f;
            #pragma unroll
            for (int jx = 0; jx < 4; jx++) {
                float p = __expf(ac[iy][jx] - mnew[iy]);
                ac[iy][jx] = p;
                rs += p;
            }
            #pragma unroll
            for (int off = 8; off > 0; off >>= 1)
                rs += __shfl_xor_sync(0xffffffffu, rs, off);
            rsum[iy] = rs;
        }
        #pragma unroll
        for (int iy = 0; iy < 4; iy++) {
            float corr = __expf(mrun[iy] - mnew[iy]);
            lsum[iy] = lsum[iy] * corr + rsum[iy];
            mrun[iy] = mnew[iy];
            #pragma unroll
            for (int jx = 0; jx < 4; jx++) out[iy][jx] *= corr;
        }

        __syncthreads();   // kT reads done -> reuse as Pt
        #pragma unroll
        for (int jx = 0; jx < 4; jx++) {
            float4 pv = make_float4(ac[0][jx], ac[1][jx], ac[2][jx], ac[3][jx]);
            *reinterpret_cast<float4*>(&kT[(tx*4 + jx)*QU_S + ty*4]) = pv;
        }
        __syncthreads();

        // ---- out += P @ V ----
        #pragma unroll 8
        for (int j = 0; j < 64; j++) {
            float4 pa = *reinterpret_cast<const float4*>(&kT[j*QU_S + ty*4]);
            float4 vb = *reinterpret_cast<const float4*>(&vs[j*64 + tx*4]);
            float pv[4] = {pa.x, pa.y, pa.z, pa.w};
            float vv[4] = {vb.x, vb.y, vb.z, vb.w};
            #pragma unroll
            for (int iy = 0; iy < 4; iy++)
                #pragma unroll
                for (int jx = 0; jx < 4; jx++)
                    out[iy][jx] = fmaf(pv[iy], vv[jx], out[iy][jx]);
        }
    }

    // ---- epilogue: normalize, write attn_vec ----
    #pragma unroll
    for (int iy = 0; iy < 4; iy++) {
        float inv = 1.f / lsum[iy];
        float4 o = make_float4(out[iy][0]*inv, out[iy][1]*inv, out[iy][2]*inv, out[iy][3]*inv);
        *reinterpret_cast<float4*>(&g_av[(b*QLEN + i0 + ty*4 + iy)*DM + n*DH + tx*4]) = o;
    }
}

// ---------------- launch ----------------
extern "C" void kernel_launch(void* const* d_in, const int* in_sizes, int n_in,
                              void* d_out, int out_size)
{
    (void)in_sizes; (void)n_in; (void)out_size;
    const float* x   = (const float*)d_in[0];
    const float* mem = (const float*)d_in[1];
    const float* pos = (const float*)d_in[2];
    // d_in[3] = attn_mask (deterministic: j > i + MLEN), recomputed analytically
    const float* Wq  = (const float*)d_in[4];
    const float* Wk  = (const float*)d_in[5];
    const float* Wv  = (const float*)d_in[6];
    const float* Wr  = (const float*)d_in[7];
    const float* Wo  = (const float*)d_in[8];
    const float* rwb = (const float*)d_in[9];
    const float* rrb = (const float*)d_in[10];
    float* out = (float*)d_out;

    float *pkin, *pq, *pk, *pv, *pr, *pav;
    cudaGetSymbolAddress((void**)&pkin, g_kin);
    cudaGetSymbolAddress((void**)&pq,   g_q);
    cudaGetSymbolAddress((void**)&pk,   g_k);
    cudaGetSymbolAddress((void**)&pv,   g_v);
    cudaGetSymbolAddress((void**)&pr,   g_r);
    cudaGetSymbolAddress((void**)&pav,  g_av);

    concat_kernel<<<(BSZ*KLEN*DM/4 + 255)/256, 256>>>(mem, x);

    gemm_nt<<<dim3(DM/128, BSZ*QLEN/128), 256>>>(x,    Wq, pq,  BSZ*QLEN, DM, DM);
    gemm_nt<<<dim3(DM/128, BSZ*KLEN/128), 256>>>(pkin, Wk, pk,  BSZ*KLEN, DM, DM);
    gemm_nt<<<dim3(DM/128, BSZ*KLEN/128), 256>>>(pkin, Wv, pv,  BSZ*KLEN, DM, DM);
    gemm_nt<<<dim3(DM/128, KLEN/128),     256>>>(pos,  Wr, pr,  KLEN,     DM, DM);

    cudaFuncSetAttribute(attn_kernel, cudaFuncAttributeMaxDynamicSharedMemorySize, SM_TOTF*4);
    attn_kernel<<<dim3(QLEN/64, BSZ*NH), 256, SM_TOTF*4>>>(rwb, rrb);

    gemm_nt<<<dim3(DM/128, BSZ*QLEN/128), 256>>>(pav, Wo, out, BSZ*QLEN, DM, DM);
}

// round 3
// speedup vs baseline: 1.2037x; 1.2037x over previous
#include <cuda_runtime.h>
#include <cstdint>
#include <math.h>

#define BSZ 2
#define QLEN 1024
#define MLEN 1024
#define KLEN 2048
#define NH 16
#define DH 64
#define DM 1024

// ---------------- scratch (device globals; no allocation allowed) ----------------
__device__ float g_kin[BSZ*KLEN*DM];
__device__ float g_q  [BSZ*QLEN*DM];
__device__ float g_k  [BSZ*KLEN*DM];
__device__ float g_v  [BSZ*KLEN*DM];
__device__ float g_r  [KLEN*DM];
__device__ float g_av [BSZ*QLEN*DM];

// ======================= helpers (family-common PTX only) =======================
__device__ __forceinline__ uint32_t smem_to_u32(const void* p) {
    uint32_t a;
    asm("{ .reg .u64 t; cvta.to.shared.u64 t, %1; cvt.u32.u64 %0, t; }" : "=r"(a) : "l"(p));
    return a;
}
#define CP_ASYNC16(dst, src) \
    asm volatile("cp.async.cg.shared.global [%0], [%1], 16;" :: "r"(dst), "l"(src) : "memory")
#define CP_COMMIT() asm volatile("cp.async.commit_group;" ::: "memory")
#define CP_WAIT1()  asm volatile("cp.async.wait_group 1;" ::: "memory")

#define MMA_TF32(d, a, b) \
    asm volatile("mma.sync.aligned.m16n8k8.row.col.f32.tf32.tf32.f32 " \
        "{%0,%1,%2,%3}, {%4,%5,%6,%7}, {%8,%9}, {%0,%1,%2,%3};" \
        : "+f"((d)[0]), "+f"((d)[1]), "+f"((d)[2]), "+f"((d)[3]) \
        : "r"((a)[0]), "r"((a)[1]), "r"((a)[2]), "r"((a)[3]), \
          "r"((b)[0]), "r"((b)[1]))

__device__ __forceinline__ void split_tf32(float x, uint32_t& hi, uint32_t& lo) {
    uint32_t h;
    asm("cvt.rna.tf32.f32 %0, %1;" : "=r"(h) : "f"(x));
    float lf = x - __uint_as_float(h);
    uint32_t l;
    asm("cvt.rna.tf32.f32 %0, %1;" : "=r"(l) : "f"(lf));
    hi = h; lo = l;
}

// ---------------- concat kernel ----------------
__global__ void concat_kernel(const float* __restrict__ mem, const float* __restrict__ x) {
    int idx = blockIdx.x * blockDim.x + threadIdx.x;
    const int total = BSZ*KLEN*DM/4;
    if (idx >= total) return;
    int e4   = idx & (DM/4 - 1);
    int rest = idx / (DM/4);
    int j = rest & (KLEN - 1);
    int b = rest >> 11;
    float4 v;
    if (j < MLEN) v = reinterpret_cast<const float4*>(mem)[(b*MLEN + j)*(DM/4) + e4];
    else          v = reinterpret_cast<const float4*>(x)[(b*QLEN + (j - MLEN))*(DM/4) + e4];
    reinterpret_cast<float4*>(g_kin)[idx] = v;
}

// ================= mma.sync 3xTF32 NT GEMM: C[M,N] = A[M,K]*B[N,K]^T =================
// 128x128 CTA tile, BK=16, 3-stage cp.async pipeline.
// smem rows padded to 20 floats (80B) -> conflict-free 32-bit fragment LDS.
#define GBK 16
#define ROWF 20
#define ATILEF (128*ROWF)          // 2560 floats
#define STGF   (2*ATILEF)          // 5120 floats / stage (A then B)
#define GEMM_SMEMB (3*STGF*4)      // 61440 bytes

__global__ __launch_bounds__(256) void gemm_mma(
    const float* __restrict__ A, const float* __restrict__ Bm,
    float* __restrict__ C, int M, int N, int K)
{
    extern __shared__ float sm[];
    const int tid = threadIdx.x;
    const int wid = tid >> 5, lane = tid & 31;
    const int m0 = blockIdx.y * 128, n0 = blockIdx.x * 128;
    const int wm = (wid >> 2) * 64, wn = (wid & 3) * 32;
    const int r = lane >> 2, c = lane & 3;
    const uint32_t sbase = smem_to_u32(sm);

    float acc[4][4][4];
    #pragma unroll
    for (int i = 0; i < 4; i++)
        #pragma unroll
        for (int j = 0; j < 4; j++)
            #pragma unroll
            for (int q = 0; q < 4; q++) acc[i][j][q] = 0.f;

    const int nK = K / GBK;

    // precompute this thread's 4 load slots
    int l_isB[4], l_row[4], l_q[4];
    #pragma unroll
    for (int i = 0; i < 4; i++) {
        int idx = i * 256 + tid;
        l_isB[i] = idx >> 9;
        l_row[i] = (idx >> 2) & 127;
        l_q[i]   = idx & 3;
    }

    #define ISSUE_LOAD(kt) do { \
        int _s = (kt) % 3; \
        uint32_t _stb = sbase + (uint32_t)_s * (STGF*4); \
        int _k0 = (kt) * GBK; \
        _Pragma("unroll") \
        for (int _i = 0; _i < 4; _i++) { \
            const float* _src = (l_isB[_i] ? Bm + (size_t)(n0 + l_row[_i])*K \
                                           : A  + (size_t)(m0 + l_row[_i])*K) + _k0 + l_q[_i]*4; \
            uint32_t _dst = _stb + (uint32_t)(l_isB[_i]*ATILEF + l_row[_i]*ROWF + l_q[_i]*4) * 4; \
            CP_ASYNC16(_dst, _src); \
        } \
    } while (0)

    ISSUE_LOAD(0); CP_COMMIT();
    ISSUE_LOAD(1); CP_COMMIT();

    for (int kt = 0; kt < nK; kt++) {
        CP_WAIT1();
        __syncthreads();
        if (kt + 2 < nK) { ISSUE_LOAD(kt + 2); }
        CP_COMMIT();

        const float* Ab = sm + (kt % 3) * STGF;
        const float* Bb = Ab + ATILEF;

        #pragma unroll
        for (int k8 = 0; k8 < GBK; k8 += 8) {
            uint32_t ahi[4][4], alo[4][4], bhi[4][2], blo[4][2];
            #pragma unroll
            for (int mt = 0; mt < 4; mt++) {
                const float* ar = Ab + (wm + mt*16 + r) * ROWF + k8 + c;
                split_tf32(ar[0],          ahi[mt][0], alo[mt][0]);
                split_tf32(ar[8*ROWF],     ahi[mt][1], alo[mt][1]);
                split_tf32(ar[4],          ahi[mt][2], alo[mt][2]);
                split_tf32(ar[8*ROWF + 4], ahi[mt][3], alo[mt][3]);
            }
            #pragma unroll
            for (int nt = 0; nt < 4; nt++) {
                const float* br = Bb + (wn + nt*8 + r) * ROWF + k8 + c;
                split_tf32(br[0], bhi[nt][0], blo[nt][0]);
                split_tf32(br[4], bhi[nt][1], blo[nt][1]);
            }
            #pragma unroll
            for (int mt = 0; mt < 4; mt++)
                #pragma unroll
                for (int nt = 0; nt < 4; nt++) {
                    MMA_TF32(acc[mt][nt], ahi[mt], bhi[nt]);
                    MMA_TF32(acc[mt][nt], ahi[mt], blo[nt]);
                    MMA_TF32(acc[mt][nt], alo[mt], bhi[nt]);
                }
        }
    }

    // epilogue
    #pragma unroll
    for (int mt = 0; mt < 4; mt++) {
        int row = m0 + wm + mt*16 + r;
        #pragma unroll
        for (int nt = 0; nt < 4; nt++) {
            int col = n0 + wn + nt*8 + 2*c;
            *reinterpret_cast<float2*>(&C[(size_t)row*N + col]) =
                make_float2(acc[mt][nt][0], acc[mt][nt][1]);
            *reinterpret_cast<float2*>(&C[(size_t)(row+8)*N + col]) =
                make_float2(acc[mt][nt][2], acc[mt][nt][3]);
        }
    }
}

// ---------------- fused relative attention (flash style, unchanged) ----------------
#define QU_S 68
#define RT_S 128
#define SM_QU 0
#define SM_QV 4352
#define SM_KT 8704
#define SM_VS 13056
#define SM_RT 17152
#define SM_TOTF (17152 + 64*RT_S)

__global__ __launch_bounds__(256, 2) void attn_kernel(
    const float* __restrict__ r_w_bias, const float* __restrict__ r_r_bias)
{
    extern __shared__ float smemf[];
    float* quT = smemf + SM_QU;
    float* qvT = smemf + SM_QV;
    float* kT  = smemf + SM_KT;
    float* vs  = smemf + SM_VS;
    float* rT  = smemf + SM_RT;

    const int tid = threadIdx.x;
    const int tx = tid & 15, ty = tid >> 4;
    const int i0 = blockIdx.x * 64;
    const int bn = blockIdx.y;
    const int b = bn >> 4, n = bn & 15;

    {
        int ii = tid >> 2, c = tid & 3;
        const float* qrow = g_q + (b*QLEN + i0 + ii)*DM + n*DH;
        const float4* ub = reinterpret_cast<const float4*>(r_w_bias + n*DH);
        const float4* vb = reinterpret_cast<const float4*>(r_r_bias + n*DH);
        #pragma unroll
        for (int r = 0; r < 4; r++) {
            int d4 = c + r*4;
            float4 q4 = reinterpret_cast<const float4*>(qrow)[d4];
            float4 u4 = ub[d4];
            float4 v4 = vb[d4];
            quT[(d4*4+0)*QU_S + ii] = q4.x + u4.x;
            quT[(d4*4+1)*QU_S + ii] = q4.y + u4.y;
            quT[(d4*4+2)*QU_S + ii] = q4.z + u4.z;
            quT[(d4*4+3)*QU_S + ii] = q4.w + u4.w;
            qvT[(d4*4+0)*QU_S + ii] = q4.x + v4.x;
            qvT[(d4*4+1)*QU_S + ii] = q4.y + v4.y;
            qvT[(d4*4+2)*QU_S + ii] = q4.z + v4.z;
            qvT[(d4*4+3)*QU_S + ii] = q4.w + v4.w;
        }
    }

    float out[4][4];
    #pragma unroll
    for (int i = 0; i < 4; i++)
        #pragma unroll
        for (int j = 0; j < 4; j++) out[i][j] = 0.f;
    float lsum[4] = {0.f, 0.f, 0.f, 0.f};
    float mrun[4] = {-1e30f, -1e30f, -1e30f, -1e30f};

    const int ntiles = i0/64 + 17;
    const int rbase = 4*(tx - ty + 15);

    for (int kt = 0; kt < ntiles; kt++) {
        const int j0 = kt * 64;
        __syncthreads();

        {
            int jj = tid >> 2, c = tid & 3;
            const float* krow = g_k + (b*KLEN + j0 + jj)*DM + n*DH;
            const float* vrow = g_v + (b*KLEN + j0 + jj)*DM + n*DH;
            #pragma unroll
            for (int r = 0; r < 4; r++) {
                int d4 = c + r*4;
                float4 k4 = reinterpret_cast<const float4*>(krow)[d4];
                kT[(d4*4+0)*QU_S + jj] = k4.x;
                kT[(d4*4+1)*QU_S + jj] = k4.y;
                kT[(d4*4+2)*QU_S + jj] = k4.z;
                kT[(d4*4+3)*QU_S + jj] = k4.w;
                float4 v4 = reinterpret_cast<const float4*>(vrow)[d4];
                *reinterpret_cast<float4*>(&vs[jj*64 + d4*4]) = v4;
            }
        }
        {
            int t = tid >> 1, c = tid & 1;
            int rel = (j0 - i0 + 960) + t;
            rel = rel < 0 ? 0 : (rel > KLEN-1 ? KLEN-1 : rel);
            const float* rrow = g_r + rel*DM + n*DH;
            #pragma unroll
            for (int r8 = 0; r8 < 8; r8++) {
                int d4 = c*8 + r8;
                float4 r4 = reinterpret_cast<const float4*>(rrow)[d4];
                rT[(d4*4+0)*RT_S + t] = r4.x;
                rT[(d4*4+1)*RT_S + t] = r4.y;
                rT[(d4*4+2)*RT_S + t] = r4.z;
                rT[(d4*4+3)*RT_S + t] = r4.w;
            }
        }
        __syncthreads();

        float ac[4][4], bd[4][4];
        #pragma unroll
        for (int i = 0; i < 4; i++)
            #pragma unroll
            for (int j = 0; j < 4; j++) { ac[i][j] = 0.f; bd[i][j] = 0.f; }

        #pragma unroll 4
        for (int d = 0; d < DH; d++) {
            float4 a4 = *reinterpret_cast<const float4*>(&quT[d*QU_S + ty*4]);
            float4 k4 = *reinterpret_cast<const float4*>(&kT [d*QU_S + tx*4]);
            float4 c4 = *reinterpret_cast<const float4*>(&qvT[d*QU_S + ty*4]);
            float4 r0 = *reinterpret_cast<const float4*>(&rT [d*RT_S + rbase]);
            float4 r1 = *reinterpret_cast<const float4*>(&rT [d*RT_S + rbase + 4]);
            float av[4] = {a4.x, a4.y, a4.z, a4.w};
            float kv[4] = {k4.x, k4.y, k4.z, k4.w};
            float cv[4] = {c4.x, c4.y, c4.z, c4.w};
            float rv[8] = {r0.x, r0.y, r0.z, r0.w, r1.x, r1.y, r1.z, r1.w};
            #pragma unroll
            for (int iy = 0; iy < 4; iy++)
                #pragma unroll
                for (int jx = 0; jx < 4; jx++) {
                    ac[iy][jx] = fmaf(av[iy], kv[jx], ac[iy][jx]);
                    bd[iy][jx] = fmaf(cv[iy], rv[jx - iy + 3], bd[iy][jx]);
                }
        }

        #pragma unroll
        for (int iy = 0; iy < 4; iy++) {
            int ii = i0 + ty*4 + iy;
            #pragma unroll
            for (int jx = 0; jx < 4; jx++) {
                float s = (ac[iy][jx] + bd[iy][jx]) * 0.125f;
                if (j0 + tx*4 + jx > ii + MLEN) s = -1e30f;
                ac[iy][jx] = s;
            }
        }
        float mnew[4], rsum[4];
        #pragma unroll
        for (int iy = 0; iy < 4; iy++) {
            float tm = fmaxf(fmaxf(ac[iy][0], ac[iy][1]), fmaxf(ac[iy][2], ac[iy][3]));
            #pragma unroll
            for (int off = 8; off > 0; off >>= 1)
                tm = fmaxf(tm, __shfl_xor_sync(0xffffffffu, tm, off));
            mnew[iy] = fmaxf(mrun[iy], tm);
            float rs = 0.f;
            #pragma unroll
            for (int jx = 0; jx < 4; jx++) {
                float p = __expf(ac[iy][jx] - mnew[iy]);
                ac[iy][jx] = p;
                rs += p;
            }
            #pragma unroll
            for (int off = 8; off > 0; off >>= 1)
                rs += __shfl_xor_sync(0xffffffffu, rs, off);
            rsum[iy] = rs;
        }
        #pragma unroll
        for (int iy = 0; iy < 4; iy++) {
            float corr = __expf(mrun[iy] - mnew[iy]);
            lsum[iy] = lsum[iy] * corr + rsum[iy];
            mrun[iy] = mnew[iy];
            #pragma unroll
            for (int jx = 0; jx < 4; jx++) out[iy][jx] *= corr;
        }

        __syncthreads();
        #pragma unroll
        for (int jx = 0; jx < 4; jx++) {
            float4 pv = make_float4(ac[0][jx], ac[1][jx], ac[2][jx], ac[3][jx]);
            *reinterpret_cast<float4*>(&kT[(tx*4 + jx)*QU_S + ty*4]) = pv;
        }
        __syncthreads();

        #pragma unroll 8
        for (int j = 0; j < 64; j++) {
            float4 pa = *reinterpret_cast<const float4*>(&kT[j*QU_S + ty*4]);
            float4 vb = *reinterpret_cast<const float4*>(&vs[j*64 + tx*4]);
            float pv[4] = {pa.x, pa.y, pa.z, pa.w};
            float vv[4] = {vb.x, vb.y, vb.z, vb.w};
            #pragma unroll
            for (int iy = 0; iy < 4; iy++)
                #pragma unroll
                for (int jx = 0; jx < 4; jx++)
                    out[iy][jx] = fmaf(pv[iy], vv[jx], out[iy][jx]);
        }
    }

    #pragma unroll
    for (int iy = 0; iy < 4; iy++) {
        float inv = 1.f / lsum[iy];
        float4 o = make_float4(out[iy][0]*inv, out[iy][1]*inv, out[iy][2]*inv, out[iy][3]*inv);
        *reinterpret_cast<float4*>(&g_av[(b*QLEN + i0 + ty*4 + iy)*DM + n*DH + tx*4]) = o;
    }
}

// ---------------- launch ----------------
extern "C" void kernel_launch(void* const* d_in, const int* in_sizes, int n_in,
                              void* d_out, int out_size)
{
    (void)in_sizes; (void)n_in; (void)out_size;
    const float* x   = (const float*)d_in[0];
    const float* mem = (const float*)d_in[1];
    const float* pos = (const float*)d_in[2];
    const float* Wq  = (const float*)d_in[4];
    const float* Wk  = (const float*)d_in[5];
    const float* Wv  = (const float*)d_in[6];
    const float* Wr  = (const float*)d_in[7];
    const float* Wo  = (const float*)d_in[8];
    const float* rwb = (const float*)d_in[9];
    const float* rrb = (const float*)d_in[10];
    float* out = (float*)d_out;

    float *pkin, *pq, *pk, *pv, *pr, *pav;
    cudaGetSymbolAddress((void**)&pkin, g_kin);
    cudaGetSymbolAddress((void**)&pq,   g_q);
    cudaGetSymbolAddress((void**)&pk,   g_k);
    cudaGetSymbolAddress((void**)&pv,   g_v);
    cudaGetSymbolAddress((void**)&pr,   g_r);
    cudaGetSymbolAddress((void**)&pav,  g_av);

    concat_kernel<<<(BSZ*KLEN*DM/4 + 255)/256, 256>>>(mem, x);

    cudaFuncSetAttribute(gemm_mma, cudaFuncAttributeMaxDynamicSharedMemorySize, GEMM_SMEMB);
    gemm_mma<<<dim3(DM/128, BSZ*QLEN/128), 256, GEMM_SMEMB>>>(x,    Wq, pq,  BSZ*QLEN, DM, DM);
    gemm_mma<<<dim3(DM/128, BSZ*KLEN/128), 256, GEMM_SMEMB>>>(pkin, Wk, pk,  BSZ*KLEN, DM, DM);
    gemm_mma<<<dim3(DM/128, BSZ*KLEN/128), 256, GEMM_SMEMB>>>(pkin, Wv, pv,  BSZ*KLEN, DM, DM);
    gemm_mma<<<dim3(DM/128, KLEN/128),     256, GEMM_SMEMB>>>(pos,  Wr, pr,  KLEN,     DM, DM);

    cudaFuncSetAttribute(attn_kernel, cudaFuncAttributeMaxDynamicSharedMemorySize, SM_TOTF*4);
    attn_kernel<<<dim3(QLEN/64, BSZ*NH), 256, SM_TOTF*4>>>(rwb, rrb);

    gemm_mma<<<dim3(DM/128, BSZ*QLEN/128), 256, GEMM_SMEMB>>>(pav, Wo, out, BSZ*QLEN, DM, DM);
}

// round 4
// speedup vs baseline: 1.2168x; 1.0109x over previous
#include <cuda_runtime.h>
#include <cstdint>
#include <math.h>

#define BSZ 2
#define QLEN 1024
#define MLEN 1024
#define KLEN 2048
#define NH 16
#define DH 64
#define DM 1024

// ---------------- scratch (device globals; no allocation allowed) ----------------
__device__ float g_kin[BSZ*KLEN*DM];
__device__ float g_q  [BSZ*QLEN*DM];
__device__ float g_k  [BSZ*KLEN*DM];
__device__ float g_v  [BSZ*KLEN*DM];
__device__ float g_r  [KLEN*DM];
__device__ float g_av [BSZ*QLEN*DM];

// ======================= helpers (family-common PTX only) =======================
__device__ __forceinline__ uint32_t smem_to_u32(const void* p) {
    uint32_t a;
    asm("{ .reg .u64 t; cvta.to.shared.u64 t, %1; cvt.u32.u64 %0, t; }" : "=r"(a) : "l"(p));
    return a;
}
#define CP_ASYNC16(dst, src) \
    asm volatile("cp.async.cg.shared.global [%0], [%1], 16;" :: "r"(dst), "l"(src) : "memory")
#define CP_COMMIT() asm volatile("cp.async.commit_group;" ::: "memory")
#define CP_WAIT1()  asm volatile("cp.async.wait_group 1;" ::: "memory")

#define MMA_TF32(d, a, b) \
    asm volatile("mma.sync.aligned.m16n8k8.row.col.f32.tf32.tf32.f32 " \
        "{%0,%1,%2,%3}, {%4,%5,%6,%7}, {%8,%9}, {%0,%1,%2,%3};" \
        : "+f"((d)[0]), "+f"((d)[1]), "+f"((d)[2]), "+f"((d)[3]) \
        : "r"((a)[0]), "r"((a)[1]), "r"((a)[2]), "r"((a)[3]), \
          "r"((b)[0]), "r"((b)[1]))

__device__ __forceinline__ void split_tf32(float x, uint32_t& hi, uint32_t& lo) {
    uint32_t h;
    asm("cvt.rna.tf32.f32 %0, %1;" : "=r"(h) : "f"(x));
    float lf = x - __uint_as_float(h);
    uint32_t l;
    asm("cvt.rna.tf32.f32 %0, %1;" : "=r"(l) : "f"(lf));
    hi = h; lo = l;
}

// ---------------- concat kernel ----------------
__global__ void concat_kernel(const float* __restrict__ mem, const float* __restrict__ x) {
    int idx = blockIdx.x * blockDim.x + threadIdx.x;
    const int total = BSZ*KLEN*DM/4;
    if (idx >= total) return;
    int e4   = idx & (DM/4 - 1);
    int rest = idx / (DM/4);
    int j = rest & (KLEN - 1);
    int b = rest >> 11;
    float4 v;
    if (j < MLEN) v = reinterpret_cast<const float4*>(mem)[(b*MLEN + j)*(DM/4) + e4];
    else          v = reinterpret_cast<const float4*>(x)[(b*QLEN + (j - MLEN))*(DM/4) + e4];
    reinterpret_cast<float4*>(g_kin)[idx] = v;
}

// ================= mma.sync 3xTF32 NT GEMM: C[M,N] = A[M,K]*B[N,K]^T =================
// 128x128 CTA tile, BK=16, 3-stage cp.async pipeline.
// smem rows padded to 20 floats (80B) -> conflict-free 32-bit fragment LDS.
#define GBK 16
#define ROWF 20
#define ATILEF (128*ROWF)          // 2560 floats
#define STGF   (2*ATILEF)          // 5120 floats / stage (A then B)
#define GEMM_SMEMB (3*STGF*4)      // 61440 bytes

__global__ __launch_bounds__(256) void gemm_mma(
    const float* __restrict__ A, const float* __restrict__ Bm,
    float* __restrict__ C, int M, int N, int K)
{
    extern __shared__ float sm[];
    const int tid = threadIdx.x;
    const int wid = tid >> 5, lane = tid & 31;
    const int m0 = blockIdx.y * 128, n0 = blockIdx.x * 128;
    const int wm = (wid >> 2) * 64, wn = (wid & 3) * 32;
    const int r = lane >> 2, c = lane & 3;
    const uint32_t sbase = smem_to_u32(sm);

    float acc[4][4][4];
    #pragma unroll
    for (int i = 0; i < 4; i++)
        #pragma unroll
        for (int j = 0; j < 4; j++)
            #pragma unroll
            for (int q = 0; q < 4; q++) acc[i][j][q] = 0.f;

    const int nK = K / GBK;

    // precompute this thread's 4 load slots
    int l_isB[4], l_row[4], l_q[4];
    #pragma unroll
    for (int i = 0; i < 4; i++) {
        int idx = i * 256 + tid;
        l_isB[i] = idx >> 9;
        l_row[i] = (idx >> 2) & 127;
        l_q[i]   = idx & 3;
    }

    #define ISSUE_LOAD(kt) do { \
        int _s = (kt) % 3; \
        uint32_t _stb = sbase + (uint32_t)_s * (STGF*4); \
        int _k0 = (kt) * GBK; \
        _Pragma("unroll") \
        for (int _i = 0; _i < 4; _i++) { \
            const float* _src = (l_isB[_i] ? Bm + (size_t)(n0 + l_row[_i])*K \
                                           : A  + (size_t)(m0 + l_row[_i])*K) + _k0 + l_q[_i]*4; \
            uint32_t _dst = _stb + (uint32_t)(l_isB[_i]*ATILEF + l_row[_i]*ROWF + l_q[_i]*4) * 4; \
            CP_ASYNC16(_dst, _src); \
        } \
    } while (0)

    ISSUE_LOAD(0); CP_COMMIT();
    ISSUE_LOAD(1); CP_COMMIT();

    for (int kt = 0; kt < nK; kt++) {
        CP_WAIT1();
        __syncthreads();
        if (kt + 2 < nK) { ISSUE_LOAD(kt + 2); }
        CP_COMMIT();

        const float* Ab = sm + (kt % 3) * STGF;
        const float* Bb = Ab + ATILEF;

        #pragma unroll
        for (int k8 = 0; k8 < GBK; k8 += 8) {
            uint32_t ahi[4][4], alo[4][4], bhi[4][2], blo[4][2];
            #pragma unroll
            for (int mt = 0; mt < 4; mt++) {
                const float* ar = Ab + (wm + mt*16 + r) * ROWF + k8 + c;
                split_tf32(ar[0],          ahi[mt][0], alo[mt][0]);
                split_tf32(ar[8*ROWF],     ahi[mt][1], alo[mt][1]);
                split_tf32(ar[4],          ahi[mt][2], alo[mt][2]);
                split_tf32(ar[8*ROWF + 4], ahi[mt][3], alo[mt][3]);
            }
            #pragma unroll
            for (int nt = 0; nt < 4; nt++) {
                const float* br = Bb + (wn + nt*8 + r) * ROWF + k8 + c;
                split_tf32(br[0], bhi[nt][0], blo[nt][0]);
                split_tf32(br[4], bhi[nt][1], blo[nt][1]);
            }
            #pragma unroll
            for (int mt = 0; mt < 4; mt++)
                #pragma unroll
                for (int nt = 0; nt < 4; nt++) {
                    MMA_TF32(acc[mt][nt], ahi[mt], bhi[nt]);
                    MMA_TF32(acc[mt][nt], ahi[mt], blo[nt]);
                    MMA_TF32(acc[mt][nt], alo[mt], bhi[nt]);
                }
        }
    }

    // epilogue
    #pragma unroll
    for (int mt = 0; mt < 4; mt++) {
        int row = m0 + wm + mt*16 + r;
        #pragma unroll
        for (int nt = 0; nt < 4; nt++) {
            int col = n0 + wn + nt*8 + 2*c;
            *reinterpret_cast<float2*>(&C[(size_t)row*N + col]) =
                make_float2(acc[mt][nt][0], acc[mt][nt][1]);
            *reinterpret_cast<float2*>(&C[(size_t)(row+8)*N + col]) =
                make_float2(acc[mt][nt][2], acc[mt][nt][3]);
        }
    }
}

// ---------------- fused relative attention (flash style, unchanged) ----------------
#define QU_S 68
#define RT_S 128
#define SM_QU 0
#define SM_QV 4352
#define SM_KT 8704
#define SM_VS 13056
#define SM_RT 17152
#define SM_TOTF (17152 + 64*RT_S)

__global__ __launch_bounds__(256, 2) void attn_kernel(
    const float* __restrict__ r_w_bias, const float* __restrict__ r_r_bias)
{
    extern __shared__ float smemf[];
    float* quT = smemf + SM_QU;
    float* qvT = smemf + SM_QV;
    float* kT  = smemf + SM_KT;
    float* vs  = smemf + SM_VS;
    float* rT  = smemf + SM_RT;

    const int tid = threadIdx.x;
    const int tx = tid & 15, ty = tid >> 4;
    const int i0 = blockIdx.x * 64;
    const int bn = blockIdx.y;
    const int b = bn >> 4, n = bn & 15;

    {
        int ii = tid >> 2, c = tid & 3;
        const float* qrow = g_q + (b*QLEN + i0 + ii)*DM + n*DH;
        const float4* ub = reinterpret_cast<const float4*>(r_w_bias + n*DH);
        const float4* vb = reinterpret_cast<const float4*>(r_r_bias + n*DH);
        #pragma unroll
        for (int r = 0; r < 4; r++) {
            int d4 = c + r*4;
            float4 q4 = reinterpret_cast<const float4*>(qrow)[d4];
            float4 u4 = ub[d4];
            float4 v4 = vb[d4];
            quT[(d4*4+0)*QU_S + ii] = q4.x + u4.x;
            quT[(d4*4+1)*QU_S + ii] = q4.y + u4.y;
            quT[(d4*4+2)*QU_S + ii] = q4.z + u4.z;
            quT[(d4*4+3)*QU_S + ii] = q4.w + u4.w;
            qvT[(d4*4+0)*QU_S + ii] = q4.x + v4.x;
            qvT[(d4*4+1)*QU_S + ii] = q4.y + v4.y;
            qvT[(d4*4+2)*QU_S + ii] = q4.z + v4.z;
            qvT[(d4*4+3)*QU_S + ii] = q4.w + v4.w;
        }
    }

    float out[4][4];
    #pragma unroll
    for (int i = 0; i < 4; i++)
        #pragma unroll
        for (int j = 0; j < 4; j++) out[i][j] = 0.f;
    float lsum[4] = {0.f, 0.f, 0.f, 0.f};
    float mrun[4] = {-1e30f, -1e30f, -1e30f, -1e30f};

    const int ntiles = i0/64 + 17;
    const int rbase = 4*(tx - ty + 15);

    for (int kt = 0; kt < ntiles; kt++) {
        const int j0 = kt * 64;
        __syncthreads();

        {
            int jj = tid >> 2, c = tid & 3;
            const float* krow = g_k + (b*KLEN + j0 + jj)*DM + n*DH;
            const float* vrow = g_v + (b*KLEN + j0 + jj)*DM + n*DH;
            #pragma unroll
            for (int r = 0; r < 4; r++) {
                int d4 = c + r*4;
                float4 k4 = reinterpret_cast<const float4*>(krow)[d4];
                kT[(d4*4+0)*QU_S + jj] = k4.x;
                kT[(d4*4+1)*QU_S + jj] = k4.y;
                kT[(d4*4+2)*QU_S + jj] = k4.z;
                kT[(d4*4+3)*QU_S + jj] = k4.w;
                float4 v4 = reinterpret_cast<const float4*>(vrow)[d4];
                *reinterpret_cast<float4*>(&vs[jj*64 + d4*4]) = v4;
            }
        }
        {
            int t = tid >> 1, c = tid & 1;
            int rel = (j0 - i0 + 960) + t;
            rel = rel < 0 ? 0 : (rel > KLEN-1 ? KLEN-1 : rel);
            const float* rrow = g_r + rel*DM + n*DH;
            #pragma unroll
            for (int r8 = 0; r8 < 8; r8++) {
                int d4 = c*8 + r8;
                float4 r4 = reinterpret_cast<const float4*>(rrow)[d4];
                rT[(d4*4+0)*RT_S + t] = r4.x;
                rT[(d4*4+1)*RT_S + t] = r4.y;
                rT[(d4*4+2)*RT_S + t] = r4.z;
                rT[(d4*4+3)*RT_S + t] = r4.w;
            }
        }
        __syncthreads();

        float ac[4][4], bd[4][4];
        #pragma unroll
        for (int i = 0; i < 4; i++)
            #pragma unroll
            for (int j = 0; j < 4; j++) { ac[i][j] = 0.f; bd[i][j] = 0.f; }

        #pragma unroll 4
        for (int d = 0; d < DH; d++) {
            float4 a4 = *reinterpret_cast<const float4*>(&quT[d*QU_S + ty*4]);
            float4 k4 = *reinterpret_cast<const float4*>(&kT [d*QU_S + tx*4]);
            float4 c4 = *reinterpret_cast<const float4*>(&qvT[d*QU_S + ty*4]);
            float4 r0 = *reinterpret_cast<const float4*>(&rT [d*RT_S + rbase]);
            float4 r1 = *reinterpret_cast<const float4*>(&rT [d*RT_S + rbase + 4]);
            float av[4] = {a4.x, a4.y, a4.z, a4.w};
            float kv[4] = {k4.x, k4.y, k4.z, k4.w};
            float cv[4] = {c4.x, c4.y, c4.z, c4.w};
            float rv[8] = {r0.x, r0.y, r0.z, r0.w, r1.x, r1.y, r1.z, r1.w};
            #pragma unroll
            for (int iy = 0; iy < 4; iy++)
                #pragma unroll
                for (int jx = 0; jx < 4; jx++) {
                    ac[iy][jx] = fmaf(av[iy], kv[jx], ac[iy][jx]);
                    bd[iy][jx] = fmaf(cv[iy], rv[jx - iy + 3], bd[iy][jx]);
                }
        }

        #pragma unroll
        for (int iy = 0; iy < 4; iy++) {
            int ii = i0 + ty*4 + iy;
            #pragma unroll
            for (int jx = 0; jx < 4; jx++) {
                float s = (ac[iy][jx] + bd[iy][jx]) * 0.125f;
                if (j0 + tx*4 + jx > ii + MLEN) s = -1e30f;
                ac[iy][jx] = s;
            }
        }
        float mnew[4], rsum[4];
        #pragma unroll
        for (int iy = 0; iy < 4; iy++) {
            float tm = fmaxf(fmaxf(ac[iy][0], ac[iy][1]), fmaxf(ac[iy][2], ac[iy][3]));
            #pragma unroll
            for (int off = 8; off > 0; off >>= 1)
                tm = fmaxf(tm, __shfl_xor_sync(0xffffffffu, tm, off));
            mnew[iy] = fmaxf(mrun[iy], tm);
            float rs = 0.f;
            #pragma unroll
            for (int jx = 0; jx < 4; jx++) {
                float p = __expf(ac[iy][jx] - mnew[iy]);
                ac[iy][jx] = p;
                rs += p;
            }
            #pragma unroll
            for (int off = 8; off > 0; off >>= 1)
                rs += __shfl_xor_sync(0xffffffffu, rs, off);
            rsum[iy] = rs;
        }
        #pragma unroll
        for (int iy = 0; iy < 4; iy++) {
            float corr = __expf(mrun[iy] - mnew[iy]);
            lsum[iy] = lsum[iy] * corr + rsum[iy];
            mrun[iy] = mnew[iy];
            #pragma unroll
            for (int jx = 0; jx < 4; jx++) out[iy][jx] *= corr;
        }

        __syncthreads();
        #pragma unroll
        for (int jx = 0; jx < 4; jx++) {
            float4 pv = make_float4(ac[0][jx], ac[1][jx], ac[2][jx], ac[3][jx]);
            *reinterpret_cast<float4*>(&kT[(tx*4 + jx)*QU_S + ty*4]) = pv;
        }
        __syncthreads();

        #pragma unroll 8
        for (int j = 0; j < 64; j++) {
            float4 pa = *reinterpret_cast<const float4*>(&kT[j*QU_S + ty*4]);
            float4 vb = *reinterpret_cast<const float4*>(&vs[j*64 + tx*4]);
            float pv[4] = {pa.x, pa.y, pa.z, pa.w};
            float vv[4] = {vb.x, vb.y, vb.z, vb.w};
            #pragma unroll
            for (int iy = 0; iy < 4; iy++)
                #pragma unroll
                for (int jx = 0; jx < 4; jx++)
                    out[iy][jx] = fmaf(pv[iy], vv[jx], out[iy][jx]);
        }
    }

    #pragma unroll
    for (int iy = 0; iy < 4; iy++) {
        float inv = 1.f / lsum[iy];
        float4 o = make_float4(out[iy][0]*inv, out[iy][1]*inv, out[iy][2]*inv, out[iy][3]*inv);
        *reinterpret_cast<float4*>(&g_av[(b*QLEN + i0 + ty*4 + iy)*DM + n*DH + tx*4]) = o;
    }
}

// ---------------- launch ----------------
extern "C" void kernel_launch(void* const* d_in, const int* in_sizes, int n_in,
                              void* d_out, int out_size)
{
    (void)in_sizes; (void)n_in; (void)out_size;
    const float* x   = (const float*)d_in[0];
    const float* mem = (const float*)d_in[1];
    const float* pos = (const float*)d_in[2];
    const float* Wq  = (const float*)d_in[4];
    const float* Wk  = (const float*)d_in[5];
    const float* Wv  = (const float*)d_in[6];
    const float* Wr  = (const float*)d_in[7];
    const float* Wo  = (const float*)d_in[8];
    const float* rwb = (const float*)d_in[9];
    const float* rrb = (const float*)d_in[10];
    float* out = (float*)d_out;

    float *pkin, *pq, *pk, *pv, *pr, *pav;
    cudaGetSymbolAddress((void**)&pkin, g_kin);
    cudaGetSymbolAddress((void**)&pq,   g_q);
    cudaGetSymbolAddress((void**)&pk,   g_k);
    cudaGetSymbolAddress((void**)&pv,   g_v);
    cudaGetSymbolAddress((void**)&pr,   g_r);
    cudaGetSymbolAddress((void**)&pav,  g_av);

    concat_kernel<<<(BSZ*KLEN*DM/4 + 255)/256, 256>>>(mem, x);

    cudaFuncSetAttribute(gemm_mma, cudaFuncAttributeMaxDynamicSharedMemorySize, GEMM_SMEMB);
    gemm_mma<<<dim3(DM/128, BSZ*QLEN/128), 256, GEMM_SMEMB>>>(x,    Wq, pq,  BSZ*QLEN, DM, DM);
    gemm_mma<<<dim3(DM/128, BSZ*KLEN/128), 256, GEMM_SMEMB>>>(pkin, Wk, pk,  BSZ*KLEN, DM, DM);
    gemm_mma<<<dim3(DM/128, BSZ*KLEN/128), 256, GEMM_SMEMB>>>(pkin, Wv, pv,  BSZ*KLEN, DM, DM);
    gemm_mma<<<dim3(DM/128, KLEN/128),     256, GEMM_SMEMB>>>(pos,  Wr, pr,  KLEN,     DM, DM);

    cudaFuncSetAttribute(attn_kernel, cudaFuncAttributeMaxDynamicSharedMemorySize, SM_TOTF*4);
    attn_kernel<<<dim3(QLEN/64, BSZ*NH), 256, SM_TOTF*4>>>(rwb, rrb);

    gemm_mma<<<dim3(DM/128, BSZ*QLEN/128), 256, GEMM_SMEMB>>>(pav, Wo, out, BSZ*QLEN, DM, DM);
}

// round 5
// speedup vs baseline: 2.3021x; 1.8918x over previous
#include <cuda_runtime.h>
#include <cuda_bf16.h>
#include <cstdint>
#include <math.h>

#define BSZ 2
#define QLEN 1024
#define MLEN 1024
#define KLEN 2048
#define NH 16
#define DH 64
#define DM 1024

typedef __nv_bfloat16 bf16;
typedef __nv_bfloat162 bf162;

// ---------------- scratch ----------------
__device__ float g_q  [BSZ*QLEN*DM];
__device__ float g_k  [BSZ*KLEN*DM];
__device__ float g_v  [BSZ*KLEN*DM];
__device__ float g_r  [KLEN*DM];
__device__ bf16 g_xhi [BSZ*QLEN*DM];
__device__ bf16 g_xlo [BSZ*QLEN*DM];
__device__ bf16 g_kihi[BSZ*KLEN*DM];
__device__ bf16 g_kilo[BSZ*KLEN*DM];
__device__ bf16 g_pohi[KLEN*DM];
__device__ bf16 g_polo[KLEN*DM];
__device__ bf16 g_whi [5*DM*DM];
__device__ bf16 g_wlo [5*DM*DM];
__device__ bf16 g_avhi[BSZ*QLEN*DM];
__device__ bf16 g_avlo[BSZ*QLEN*DM];

// ---------------- helpers ----------------
__device__ __forceinline__ uint32_t smem_to_u32(const void* p) {
    uint32_t a;
    asm("{ .reg .u64 t; cvta.to.shared.u64 t, %1; cvt.u32.u64 %0, t; }" : "=r"(a) : "l"(p));
    return a;
}
#define CP_ASYNC16(dst, src) \
    asm volatile("cp.async.cg.shared.global [%0], [%1], 16;" :: "r"(dst), "l"(src) : "memory")
#define CP_COMMIT() asm volatile("cp.async.commit_group;" ::: "memory")
#define CP_WAIT1()  asm volatile("cp.async.wait_group 1;" ::: "memory")

#define MMA_BF16(d, a, b) \
    asm volatile("mma.sync.aligned.m16n8k16.row.col.f32.bf16.bf16.f32 " \
        "{%0,%1,%2,%3}, {%4,%5,%6,%7}, {%8,%9}, {%0,%1,%2,%3};" \
        : "+f"((d)[0]), "+f"((d)[1]), "+f"((d)[2]), "+f"((d)[3]) \
        : "r"((a)[0]), "r"((a)[1]), "r"((a)[2]), "r"((a)[3]), \
          "r"((b)[0]), "r"((b)[1]))

__device__ __forceinline__ void split2(float a, float b, uint32_t& hi, uint32_t& lo) {
    bf162 h = __floats2bfloat162_rn(a, b);
    bf162 l = __floats2bfloat162_rn(a - __bfloat162float(h.x), b - __bfloat162float(h.y));
    hi = *reinterpret_cast<uint32_t*>(&h);
    lo = *reinterpret_cast<uint32_t*>(&l);
}

// ---------------- prep kernels ----------------
__global__ void split_kernel(const float* __restrict__ src, bf16* __restrict__ hi,
                             bf16* __restrict__ lo, int n4) {
    int idx = blockIdx.x * blockDim.x + threadIdx.x;
    if (idx >= n4) return;
    float4 x = reinterpret_cast<const float4*>(src)[idx];
    uint32_t h0, l0, h1, l1;
    split2(x.x, x.y, h0, l0);
    split2(x.z, x.w, h1, l1);
    reinterpret_cast<uint2*>(hi)[idx] = make_uint2(h0, h1);
    reinterpret_cast<uint2*>(lo)[idx] = make_uint2(l0, l1);
}

__global__ void concat_split_kernel(const float* __restrict__ mem, const float* __restrict__ x) {
    int idx = blockIdx.x * blockDim.x + threadIdx.x;
    if (idx >= BSZ*KLEN*DM/4) return;
    int e4   = idx & (DM/4 - 1);
    int rest = idx / (DM/4);
    int j = rest & (KLEN - 1);
    int b = rest >> 11;
    float4 v;
    if (j < MLEN) v = reinterpret_cast<const float4*>(mem)[(b*MLEN + j)*(DM/4) + e4];
    else          v = reinterpret_cast<const float4*>(x)[(b*QLEN + (j - MLEN))*(DM/4) + e4];
    uint32_t h0, l0, h1, l1;
    split2(v.x, v.y, h0, l0);
    split2(v.z, v.w, h1, l1);
    reinterpret_cast<uint2*>(g_kihi)[idx] = make_uint2(h0, h1);
    reinterpret_cast<uint2*>(g_kilo)[idx] = make_uint2(l0, l1);
}

// ================= bf16 2-split GEMM: C[M,N] = A[M,K]*B[N,K]^T =================
#define GBK 32
#define ROWB 40
#define TILEB (128*ROWB)
#define STGB (4*TILEB)
#define GEMM_SMEMB (3*STGB*2)

__global__ __launch_bounds__(256) void gemm_bf16(
    const bf16* __restrict__ Ahi, const bf16* __restrict__ Alo,
    const bf16* __restrict__ Bhi, const bf16* __restrict__ Blo,
    float* __restrict__ C, int M, int N, int K)
{
    extern __shared__ bf16 sb[];
    const int tid = threadIdx.x;
    const int wid = tid >> 5, lane = tid & 31;
    const int m0 = blockIdx.y * 128, n0 = blockIdx.x * 128;
    const int wm = (wid >> 2) * 64, wn = (wid & 3) * 32;
    const int r = lane >> 2, c = lane & 3;
    const uint32_t sbase = smem_to_u32(sb);

    float acc[4][4][4];
    #pragma unroll
    for (int i = 0; i < 4; i++)
        #pragma unroll
        for (int j = 0; j < 4; j++)
            #pragma unroll
            for (int q = 0; q < 4; q++) acc[i][j][q] = 0.f;

    const bf16* mats[4] = { Ahi + (size_t)m0*K, Alo + (size_t)m0*K,
                            Bhi + (size_t)n0*K, Blo + (size_t)n0*K };
    int l_mat[8], l_row[8], l_ch[8];
    #pragma unroll
    for (int i = 0; i < 8; i++) {
        int id = i*256 + tid;
        l_mat[i] = id >> 9; l_row[i] = (id >> 2) & 127; l_ch[i] = id & 3;
    }

    #define G_ISSUE(kt) do { \
        int _s = (kt) % 3, _k0 = (kt) * GBK; \
        _Pragma("unroll") \
        for (int _i = 0; _i < 8; _i++) { \
            const bf16* _src = mats[l_mat[_i]] + (size_t)l_row[_i]*K + _k0 + l_ch[_i]*8; \
            uint32_t _dst = sbase + (uint32_t)(_s*STGB + l_mat[_i]*TILEB + l_row[_i]*ROWB + l_ch[_i]*8)*2; \
            CP_ASYNC16(_dst, _src); \
        } \
    } while (0)

    const int nK = K / GBK;
    G_ISSUE(0); CP_COMMIT();
    G_ISSUE(1); CP_COMMIT();

    for (int kt = 0; kt < nK; kt++) {
        CP_WAIT1();
        __syncthreads();
        if (kt + 2 < nK) { G_ISSUE(kt + 2); }
        CP_COMMIT();

        const bf16* Sb = sb + (kt % 3) * STGB;
        const bf16 *Ah = Sb, *Al = Sb + TILEB, *Bh = Sb + 2*TILEB, *Bl = Sb + 3*TILEB;

        #pragma unroll
        for (int k16 = 0; k16 < GBK; k16 += 16) {
            uint32_t ah[4][4], al[4][4], bh[4][2], bl[4][2];
            #pragma unroll
            for (int mt = 0; mt < 4; mt++) {
                int ro = wm + mt*16 + r, co = k16 + 2*c;
                ah[mt][0] = *(const uint32_t*)&Ah[ro*ROWB + co];
                ah[mt][1] = *(const uint32_t*)&Ah[(ro+8)*ROWB + co];
                ah[mt][2] = *(const uint32_t*)&Ah[ro*ROWB + co + 8];
                ah[mt][3] = *(const uint32_t*)&Ah[(ro+8)*ROWB + co + 8];
                al[mt][0] = *(const uint32_t*)&Al[ro*ROWB + co];
                al[mt][1] = *(const uint32_t*)&Al[(ro+8)*ROWB + co];
                al[mt][2] = *(const uint32_t*)&Al[ro*ROWB + co + 8];
                al[mt][3] = *(const uint32_t*)&Al[(ro+8)*ROWB + co + 8];
            }
            #pragma unroll
            for (int nt = 0; nt < 4; nt++) {
                int ro = wn + nt*8 + r, co = k16 + 2*c;
                bh[nt][0] = *(const uint32_t*)&Bh[ro*ROWB + co];
                bh[nt][1] = *(const uint32_t*)&Bh[ro*ROWB + co + 8];
                bl[nt][0] = *(const uint32_t*)&Bl[ro*ROWB + co];
                bl[nt][1] = *(const uint32_t*)&Bl[ro*ROWB + co + 8];
            }
            #pragma unroll
            for (int mt = 0; mt < 4; mt++)
                #pragma unroll
                for (int nt = 0; nt < 4; nt++) {
                    MMA_BF16(acc[mt][nt], ah[mt], bh[nt]);
                    MMA_BF16(acc[mt][nt], ah[mt], bl[nt]);
                    MMA_BF16(acc[mt][nt], al[mt], bh[nt]);
                }
        }
    }
    #pragma unroll
    for (int mt = 0; mt < 4; mt++) {
        int row = m0 + wm + mt*16 + r;
        #pragma unroll
        for (int nt = 0; nt < 4; nt++) {
            int col = n0 + wn + nt*8 + 2*c;
            *reinterpret_cast<float2*>(&C[(size_t)row*N + col]) = make_float2(acc[mt][nt][0], acc[mt][nt][1]);
            *reinterpret_cast<float2*>(&C[(size_t)(row+8)*N + col]) = make_float2(acc[mt][nt][2], acc[mt][nt][3]);
        }
    }
}

// ================= tensor-core flash attention with relative positions =================
#define ST 72
#define TILE9 9216
#define OFF_BD   (12*TILE9)
#define BDS 66
#define OFF_SMAX (OFF_BD + 2*64*BDS*4)
#define OFF_SSUM (OFF_SMAX + 512)
#define ATT_SMEM (OFF_SSUM + 512)

// one 16x32 chunk of a 64x64x64 split GEMM (A rows aro.., B rows bro..)
__device__ __forceinline__ void sgemm64(const bf16* __restrict__ Ah, const bf16* __restrict__ Al,
                                        const bf16* __restrict__ Bh, const bf16* __restrict__ Bl,
                                        int aro, int bro, int r, int c, float acc[4][4])
{
    #pragma unroll
    for (int kc = 0; kc < 4; kc++) {
        int co = kc*16 + 2*c;
        uint32_t ah[4], al[4];
        ah[0] = *(const uint32_t*)&Ah[(aro+r)*ST + co];
        ah[1] = *(const uint32_t*)&Ah[(aro+r+8)*ST + co];
        ah[2] = *(const uint32_t*)&Ah[(aro+r)*ST + co + 8];
        ah[3] = *(const uint32_t*)&Ah[(aro+r+8)*ST + co + 8];
        al[0] = *(const uint32_t*)&Al[(aro+r)*ST + co];
        al[1] = *(const uint32_t*)&Al[(aro+r+8)*ST + co];
        al[2] = *(const uint32_t*)&Al[(aro+r)*ST + co + 8];
        al[3] = *(const uint32_t*)&Al[(aro+r+8)*ST + co + 8];
        #pragma unroll
        for (int nt = 0; nt < 4; nt++) {
            int bo = bro + nt*8 + r;
            uint32_t bh[2], bl[2];
            bh[0] = *(const uint32_t*)&Bh[bo*ST + co]; bh[1] = *(const uint32_t*)&Bh[bo*ST + co + 8];
            bl[0] = *(const uint32_t*)&Bl[bo*ST + co]; bl[1] = *(const uint32_t*)&Bl[bo*ST + co + 8];
            MMA_BF16(acc[nt], ah, bh);
            MMA_BF16(acc[nt], ah, bl);
            MMA_BF16(acc[nt], al, bh);
        }
    }
}

// load 16 floats of one row, split, store to hi/lo smem tiles (optionally scaled+biased)
__device__ __forceinline__ void row_split16(const float* __restrict__ src, bf16* dh, bf16* dl,
                                            int row, int d0) {
    #pragma unroll
    for (int p = 0; p < 4; p++) {
        float4 v = reinterpret_cast<const float4*>(src)[p];
        int dd = d0 + p*4;
        uint32_t h, l;
        split2(v.x, v.y, h, l);
        *(uint32_t*)&dh[row*ST + dd] = h; *(uint32_t*)&dl[row*ST + dd] = l;
        split2(v.z, v.w, h, l);
        *(uint32_t*)&dh[row*ST + dd + 2] = h; *(uint32_t*)&dl[row*ST + dd + 2] = l;
    }
}

__global__ __launch_bounds__(256, 1) void attn_mma_kernel(
    const float* __restrict__ r_w_bias, const float* __restrict__ r_r_bias)
{
    extern __shared__ char smc[];
    bf16* quhi = (bf16*)(smc);             bf16* qulo = (bf16*)(smc + 1*TILE9);
    bf16* qvhi = (bf16*)(smc + 2*TILE9);   bf16* qvlo = (bf16*)(smc + 3*TILE9);
    bf16* khi  = (bf16*)(smc + 4*TILE9);   bf16* klo  = (bf16*)(smc + 5*TILE9);
    bf16* vthi = (bf16*)(smc + 6*TILE9);   bf16* vtlo = (bf16*)(smc + 7*TILE9);
    bf16* rbhi = (bf16*)(smc + 8*TILE9);   bf16* rblo = (bf16*)(smc + 9*TILE9);
    bf16* phis = (bf16*)(smc + 10*TILE9);  bf16* plos = (bf16*)(smc + 11*TILE9);
    float* bds  = (float*)(smc + OFF_BD);
    float* smax = (float*)(smc + OFF_SMAX);
    float* ssum = (float*)(smc + OFF_SSUM);

    const int tid = threadIdx.x;
    const int w = tid >> 5, lane = tid & 31;
    const int mt = w & 3, jh = w >> 2;
    const int r = lane >> 2, c = lane & 3;
    const int i0 = (15 - (int)blockIdx.x) * 64;
    const int b = blockIdx.y >> 4, hh = blockIdx.y & 15;
    const int lrow = tid >> 2;
    const int dseg = (tid & 3) * 16;
    const int aro = mt*16, bro = jh*32;

    // ---- q tile: add biases, scale by 1/8, split ----
    {
        const float* qrow = g_q + ((size_t)(b*QLEN + i0 + lrow))*DM + hh*DH + dseg;
        const float* ub = r_w_bias + hh*DH + dseg;
        const float* vb = r_r_bias + hh*DH + dseg;
        #pragma unroll
        for (int p = 0; p < 4; p++) {
            float4 q4 = reinterpret_cast<const float4*>(qrow)[p];
            float4 u4 = reinterpret_cast<const float4*>(ub)[p];
            float4 v4 = reinterpret_cast<const float4*>(vb)[p];
            int dd = dseg + p*4;
            uint32_t h, l;
            split2((q4.x+u4.x)*0.125f, (q4.y+u4.y)*0.125f, h, l);
            *(uint32_t*)&quhi[lrow*ST+dd] = h; *(uint32_t*)&qulo[lrow*ST+dd] = l;
            split2((q4.z+u4.z)*0.125f, (q4.w+u4.w)*0.125f, h, l);
            *(uint32_t*)&quhi[lrow*ST+dd+2] = h; *(uint32_t*)&qulo[lrow*ST+dd+2] = l;
            split2((q4.x+v4.x)*0.125f, (q4.y+v4.y)*0.125f, h, l);
            *(uint32_t*)&qvhi[lrow*ST+dd] = h; *(uint32_t*)&qvlo[lrow*ST+dd] = l;
            split2((q4.z+v4.z)*0.125f, (q4.w+v4.w)*0.125f, h, l);
            *(uint32_t*)&qvhi[lrow*ST+dd+2] = h; *(uint32_t*)&qvlo[lrow*ST+dd+2] = l;
        }
    }

    const int relbase0 = 960 - i0;
    const int ntiles = i0/64 + 17;

    // ---- initial BD band: buf0 = t[0,64), buf1 = t[64,128) ----
    #pragma unroll
    for (int pre = 0; pre < 2; pre++) {
        __syncthreads();
        {
            int rel = relbase0 + pre*64 + lrow;
            rel = rel < 0 ? 0 : (rel > KLEN-1 ? KLEN-1 : rel);
            row_split16(g_r + (size_t)rel*DM + hh*DH + dseg, rbhi, rblo, lrow, dseg);
        }
        __syncthreads();
        float bda[4][4];
        #pragma unroll
        for (int nt = 0; nt < 4; nt++)
            #pragma unroll
            for (int q = 0; q < 4; q++) bda[nt][q] = 0.f;
        sgemm64(qvhi, qvlo, rbhi, rblo, aro, bro, r, c, bda);
        float* bdw = bds + pre * 64 * BDS;
        #pragma unroll
        for (int nt = 0; nt < 4; nt++) {
            int tc = bro + nt*8 + 2*c;
            *reinterpret_cast<float2*>(&bdw[(aro+r)*BDS + tc]) = make_float2(bda[nt][0], bda[nt][1]);
            *reinterpret_cast<float2*>(&bdw[(aro+r+8)*BDS + tc]) = make_float2(bda[nt][2], bda[nt][3]);
        }
    }

    float out[4][4];
    #pragma unroll
    for (int nt = 0; nt < 4; nt++)
        #pragma unroll
        for (int q = 0; q < 4; q++) out[nt][q] = 0.f;
    float lsum0 = 0.f, lsum1 = 0.f, mrun0 = -1e30f, mrun1 = -1e30f;

    for (int kt = 0; kt < ntiles; kt++) {
        const int j0 = kt * 64;
        __syncthreads();

        // ---- load k (row), v (transposed), next r band ----
        {
            const float* krow = g_k + ((size_t)(b*KLEN + j0 + lrow))*DM + hh*DH + dseg;
            const float* vrow = g_v + ((size_t)(b*KLEN + j0 + lrow))*DM + hh*DH + dseg;
            row_split16(krow, khi, klo, lrow, dseg);
            #pragma unroll
            for (int p = 0; p < 4; p++) {
                float4 v4 = reinterpret_cast<const float4*>(vrow)[p];
                float vv[4] = {v4.x, v4.y, v4.z, v4.w};
                #pragma unroll
                for (int e = 0; e < 4; e++) {
                    int dd = dseg + p*4 + e;
                    bf16 hb = __float2bfloat16_rn(vv[e]);
                    vthi[dd*ST + lrow] = hb;
                    vtlo[dd*ST + lrow] = __float2bfloat16_rn(vv[e] - __bfloat162float(hb));
                }
            }
            if (kt + 1 < ntiles) {
                int rel = relbase0 + kt*64 + 128 + lrow;
                rel = rel < 0 ? 0 : (rel > KLEN-1 ? KLEN-1 : rel);
                row_split16(g_r + (size_t)rel*DM + hh*DH + dseg, rbhi, rblo, lrow, dseg);
            }
        }
        __syncthreads();

        // ---- AC scores ----
        float s[4][4];
        #pragma unroll
        for (int nt = 0; nt < 4; nt++)
            #pragma unroll
            for (int q = 0; q < 4; q++) s[nt][q] = 0.f;
        sgemm64(quhi, qulo, khi, klo, aro, bro, r, c, s);

        // ---- BD gather + mask ----
        const float* bdLo = bds + (kt & 1) * 64 * BDS;
        const float* bdHi = bds + ((kt + 1) & 1) * 64 * BDS;
        #pragma unroll
        for (int nt = 0; nt < 4; nt++)
            #pragma unroll
            for (int q = 0; q < 4; q++) {
                int il = aro + r + ((q >= 2) ? 8 : 0);
                int jl = bro + nt*8 + 2*c + (q & 1);
                int t = jl - il + 63;
                float bd = (t < 64) ? bdLo[il*BDS + t] : bdHi[il*BDS + t - 64];
                float sc = s[nt][q] + bd;
                if (j0 + jl > i0 + il + MLEN) sc = -1e30f;
                s[nt][q] = sc;
            }

        // ---- online softmax (rows split across 2 warps) ----
        float pmax0 = -1e30f, pmax1 = -1e30f;
        #pragma unroll
        for (int nt = 0; nt < 4; nt++) {
            pmax0 = fmaxf(pmax0, fmaxf(s[nt][0], s[nt][1]));
            pmax1 = fmaxf(pmax1, fmaxf(s[nt][2], s[nt][3]));
        }
        pmax0 = fmaxf(pmax0, __shfl_xor_sync(~0u, pmax0, 1));
        pmax0 = fmaxf(pmax0, __shfl_xor_sync(~0u, pmax0, 2));
        pmax1 = fmaxf(pmax1, __shfl_xor_sync(~0u, pmax1, 1));
        pmax1 = fmaxf(pmax1, __shfl_xor_sync(~0u, pmax1, 2));
        if (c == 0) {
            smax[(aro+r)*2 + jh] = pmax0;
            smax[(aro+r+8)*2 + jh] = pmax1;
        }
        __syncthreads();
        float mn0 = fmaxf(mrun0, fmaxf(pmax0, smax[(aro+r)*2 + (1-jh)]));
        float mn1 = fmaxf(mrun1, fmaxf(pmax1, smax[(aro+r+8)*2 + (1-jh)]));

        float ps0 = 0.f, ps1 = 0.f;
        #pragma unroll
        for (int nt = 0; nt < 4; nt++) {
            s[nt][0] = __expf(s[nt][0] - mn0);
            s[nt][1] = __expf(s[nt][1] - mn0);
            s[nt][2] = __expf(s[nt][2] - mn1);
            s[nt][3] = __expf(s[nt][3] - mn1);
            ps0 += s[nt][0] + s[nt][1];
            ps1 += s[nt][2] + s[nt][3];
        }
        ps0 += __shfl_xor_sync(~0u, ps0, 1); ps0 += __shfl_xor_sync(~0u, ps0, 2);
        ps1 += __shfl_xor_sync(~0u, ps1, 1); ps1 += __shfl_xor_sync(~0u, ps1, 2);
        if (c == 0) {
            ssum[(aro+r)*2 + jh] = ps0;
            ssum[(aro+r+8)*2 + jh] = ps1;
        }
        #pragma unroll
        for (int nt = 0; nt < 4; nt++) {
            int col = bro + nt*8 + 2*c;
            uint32_t h, l;
            split2(s[nt][0], s[nt][1], h, l);
            *(uint32_t*)&phis[(aro+r)*ST + col] = h;
            *(uint32_t*)&plos[(aro+r)*ST + col] = l;
            split2(s[nt][2], s[nt][3], h, l);
            *(uint32_t*)&phis[(aro+r+8)*ST + col] = h;
            *(uint32_t*)&plos[(aro+r+8)*ST + col] = l;
        }
        __syncthreads();
        float corr0 = __expf(mrun0 - mn0), corr1 = __expf(mrun1 - mn1);
        lsum0 = lsum0 * corr0 + ps0 + ssum[(aro+r)*2 + (1-jh)];
        lsum1 = lsum1 * corr1 + ps1 + ssum[(aro+r+8)*2 + (1-jh)];
        mrun0 = mn0; mrun1 = mn1;
        #pragma unroll
        for (int nt = 0; nt < 4; nt++) {
            out[nt][0] *= corr0; out[nt][1] *= corr0;
            out[nt][2] *= corr1; out[nt][3] *= corr1;
        }

        // ---- PV ----
        sgemm64(phis, plos, vthi, vtlo, aro, bro, r, c, out);

        // ---- next BD band into freed buffer ----
        if (kt + 1 < ntiles) {
            float bda[4][4];
            #pragma unroll
            for (int nt = 0; nt < 4; nt++)
                #pragma unroll
                for (int q = 0; q < 4; q++) bda[nt][q] = 0.f;
            sgemm64(qvhi, qvlo, rbhi, rblo, aro, bro, r, c, bda);
            float* bdw = bds + (kt & 1) * 64 * BDS;
            #pragma unroll
            for (int nt = 0; nt < 4; nt++) {
                int tc = bro + nt*8 + 2*c;
                *reinterpret_cast<float2*>(&bdw[(aro+r)*BDS + tc]) = make_float2(bda[nt][0], bda[nt][1]);
                *reinterpret_cast<float2*>(&bdw[(aro+r+8)*BDS + tc]) = make_float2(bda[nt][2], bda[nt][3]);
            }
        }
    }

    // ---- epilogue: normalize + split to g_av hi/lo ----
    float inv0 = 1.f / lsum0, inv1 = 1.f / lsum1;
    #pragma unroll
    for (int nt = 0; nt < 4; nt++) {
        int col = hh*DH + bro + nt*8 + 2*c;
        size_t row0 = (size_t)(b*QLEN + i0 + aro + r) * DM + col;
        size_t row1 = row0 + 8*DM;
        uint32_t h, l;
        split2(out[nt][0]*inv0, out[nt][1]*inv0, h, l);
        *(uint32_t*)&g_avhi[row0] = h; *(uint32_t*)&g_avlo[row0] = l;
        split2(out[nt][2]*inv1, out[nt][3]*inv1, h, l);
        *(uint32_t*)&g_avhi[row1] = h; *(uint32_t*)&g_avlo[row1] = l;
    }
}

// ---------------- launch ----------------
extern "C" void kernel_launch(void* const* d_in, const int* in_sizes, int n_in,
                              void* d_out, int out_size)
{
    (void)in_sizes; (void)n_in; (void)out_size;
    const float* x   = (const float*)d_in[0];
    const float* mem = (const float*)d_in[1];
    const float* pos = (const float*)d_in[2];
    const float* Wq  = (const float*)d_in[4];
    const float* Wk  = (const float*)d_in[5];
    const float* Wv  = (const float*)d_in[6];
    const float* Wr  = (const float*)d_in[7];
    const float* Wo  = (const float*)d_in[8];
    const float* rwb = (const float*)d_in[9];
    const float* rrb = (const float*)d_in[10];
    float* out = (float*)d_out;

    float *pq, *pk, *pv, *pr;
    bf16 *pxh, *pxl, *pkih, *pkil, *pph, *ppl, *pwh, *pwl, *pavh, *pavl;
    cudaGetSymbolAddress((void**)&pq,   g_q);
    cudaGetSymbolAddress((void**)&pk,   g_k);
    cudaGetSymbolAddress((void**)&pv,   g_v);
    cudaGetSymbolAddress((void**)&pr,   g_r);
    cudaGetSymbolAddress((void**)&pxh,  g_xhi);
    cudaGetSymbolAddress((void**)&pxl,  g_xlo);
    cudaGetSymbolAddress((void**)&pkih, g_kihi);
    cudaGetSymbolAddress((void**)&pkil, g_kilo);
    cudaGetSymbolAddress((void**)&pph,  g_pohi);
    cudaGetSymbolAddress((void**)&ppl,  g_polo);
    cudaGetSymbolAddress((void**)&pwh,  g_whi);
    cudaGetSymbolAddress((void**)&pwl,  g_wlo);
    cudaGetSymbolAddress((void**)&pavh, g_avhi);
    cudaGetSymbolAddress((void**)&pavl, g_avlo);

    const int WN = DM*DM;
    split_kernel<<<(BSZ*QLEN*DM/4 + 255)/256, 256>>>(x,   pxh, pxl, BSZ*QLEN*DM/4);
    split_kernel<<<(KLEN*DM/4 + 255)/256, 256>>>(pos, pph, ppl, KLEN*DM/4);
    split_kernel<<<(WN/4 + 255)/256, 256>>>(Wq, pwh + 0*WN, pwl + 0*WN, WN/4);
    split_kernel<<<(WN/4 + 255)/256, 256>>>(Wk, pwh + 1*WN, pwl + 1*WN, WN/4);
    split_kernel<<<(WN/4 + 255)/256, 256>>>(Wv, pwh + 2*WN, pwl + 2*WN, WN/4);
    split_kernel<<<(WN/4 + 255)/256, 256>>>(Wr, pwh + 3*WN, pwl + 3*WN, WN/4);
    split_kernel<<<(WN/4 + 255)/256, 256>>>(Wo, pwh + 4*WN, pwl + 4*WN, WN/4);
    concat_split_kernel<<<(BSZ*KLEN*DM/4 + 255)/256, 256>>>(mem, x);

    cudaFuncSetAttribute(gemm_bf16, cudaFuncAttributeMaxDynamicSharedMemorySize, GEMM_SMEMB);
    gemm_bf16<<<dim3(DM/128, BSZ*QLEN/128), 256, GEMM_SMEMB>>>(pxh, pxl, pwh+0*WN, pwl+0*WN, pq, BSZ*QLEN, DM, DM);
    gemm_bf16<<<dim3(DM/128, BSZ*KLEN/128), 256, GEMM_SMEMB>>>(pkih, pkil, pwh+1*WN, pwl+1*WN, pk, BSZ*KLEN, DM, DM);
    gemm_bf16<<<dim3(DM/128, BSZ*KLEN/128), 256, GEMM_SMEMB>>>(pkih, pkil, pwh+2*WN, pwl+2*WN, pv, BSZ*KLEN, DM, DM);
    gemm_bf16<<<dim3(DM/128, KLEN/128),     256, GEMM_SMEMB>>>(pph, ppl, pwh+3*WN, pwl+3*WN, pr, KLEN, DM, DM);

    cudaFuncSetAttribute(attn_mma_kernel, cudaFuncAttributeMaxDynamicSharedMemorySize, ATT_SMEM);
    attn_mma_kernel<<<dim3(QLEN/64, BSZ*NH), 256, ATT_SMEM>>>(rwb, rrb);

    // attention epilogue already produced bf16 hi/lo -> output GEMM
    gemm_bf16<<<dim3(DM/128, BSZ*QLEN/128), 256, GEMM_SMEMB>>>(pavh, pavl, pwh+4*WN, pwl+4*WN, out, BSZ*QLEN, DM, DM);
}

// round 6
// speedup vs baseline: 2.7655x; 1.2013x over previous
#include <cuda_runtime.h>
#include <cuda_bf16.h>
#include <cstdint>
#include <math.h>

#define BSZ 2
#define QLEN 1024
#define MLEN 1024
#define KLEN 2048
#define NH 16
#define DH 64
#define DM 1024

typedef __nv_bfloat16 bf16;
typedef __nv_bfloat162 bf162;

// ---------------- scratch ----------------
__device__ float g_q  [BSZ*QLEN*DM];
__device__ bf16 g_khi [BSZ*KLEN*DM];
__device__ bf16 g_klo [BSZ*KLEN*DM];
__device__ bf16 g_vhi [BSZ*KLEN*DM];
__device__ bf16 g_vlo [BSZ*KLEN*DM];
__device__ bf16 g_rhi [KLEN*DM];
__device__ bf16 g_rlo [KLEN*DM];
__device__ bf16 g_xhi [BSZ*QLEN*DM];
__device__ bf16 g_xlo [BSZ*QLEN*DM];
__device__ bf16 g_kihi[BSZ*KLEN*DM];
__device__ bf16 g_kilo[BSZ*KLEN*DM];
__device__ bf16 g_pohi[KLEN*DM];
__device__ bf16 g_polo[KLEN*DM];
__device__ bf16 g_whi [5*DM*DM];
__device__ bf16 g_wlo [5*DM*DM];
__device__ bf16 g_avhi[BSZ*QLEN*DM];
__device__ bf16 g_avlo[BSZ*QLEN*DM];

// ---------------- helpers ----------------
__device__ __forceinline__ uint32_t smem_to_u32(const void* p) {
    uint32_t a;
    asm("{ .reg .u64 t; cvta.to.shared.u64 t, %1; cvt.u32.u64 %0, t; }" : "=r"(a) : "l"(p));
    return a;
}
#define CP_ASYNC16(dst, src) \
    asm volatile("cp.async.cg.shared.global [%0], [%1], 16;" :: "r"(dst), "l"(src) : "memory")
#define CP_COMMIT() asm volatile("cp.async.commit_group;" ::: "memory")
#define CP_WAIT1()  asm volatile("cp.async.wait_group 1;" ::: "memory")
#define CP_WAIT0()  asm volatile("cp.async.wait_group 0;" ::: "memory")

#define MMA_BF16(d, a, b) \
    asm volatile("mma.sync.aligned.m16n8k16.row.col.f32.bf16.bf16.f32 " \
        "{%0,%1,%2,%3}, {%4,%5,%6,%7}, {%8,%9}, {%0,%1,%2,%3};" \
        : "+f"((d)[0]), "+f"((d)[1]), "+f"((d)[2]), "+f"((d)[3]) \
        : "r"((a)[0]), "r"((a)[1]), "r"((a)[2]), "r"((a)[3]), \
          "r"((b)[0]), "r"((b)[1]))

#define LDMX4(r0, r1, r2, r3, addr) \
    asm volatile("ldmatrix.sync.aligned.m8n8.x4.shared.b16 {%0,%1,%2,%3}, [%4];" \
        : "=r"(r0), "=r"(r1), "=r"(r2), "=r"(r3) : "r"(addr))
#define LDMX4T(r0, r1, r2, r3, addr) \
    asm volatile("ldmatrix.sync.aligned.m8n8.x4.trans.shared.b16 {%0,%1,%2,%3}, [%4];" \
        : "=r"(r0), "=r"(r1), "=r"(r2), "=r"(r3) : "r"(addr))

__device__ __forceinline__ void split2(float a, float b, uint32_t& hi, uint32_t& lo) {
    bf162 h = __floats2bfloat162_rn(a, b);
    bf162 l = __floats2bfloat162_rn(a - __bfloat162float(h.x), b - __bfloat162float(h.y));
    hi = *reinterpret_cast<uint32_t*>(&h);
    lo = *reinterpret_cast<uint32_t*>(&l);
}

// ---------------- prep kernels ----------------
__global__ void split_kernel(const float* __restrict__ src, bf16* __restrict__ hi,
                             bf16* __restrict__ lo, int n4) {
    int idx = blockIdx.x * blockDim.x + threadIdx.x;
    if (idx >= n4) return;
    float4 x = reinterpret_cast<const float4*>(src)[idx];
    uint32_t h0, l0, h1, l1;
    split2(x.x, x.y, h0, l0);
    split2(x.z, x.w, h1, l1);
    reinterpret_cast<uint2*>(hi)[idx] = make_uint2(h0, h1);
    reinterpret_cast<uint2*>(lo)[idx] = make_uint2(l0, l1);
}

__global__ void concat_split_kernel(const float* __restrict__ mem, const float* __restrict__ x) {
    int idx = blockIdx.x * blockDim.x + threadIdx.x;
    if (idx >= BSZ*KLEN*DM/4) return;
    int e4   = idx & (DM/4 - 1);
    int rest = idx / (DM/4);
    int j = rest & (KLEN - 1);
    int b = rest >> 11;
    float4 v;
    if (j < MLEN) v = reinterpret_cast<const float4*>(mem)[(b*MLEN + j)*(DM/4) + e4];
    else          v = reinterpret_cast<const float4*>(x)[(b*QLEN + (j - MLEN))*(DM/4) + e4];
    uint32_t h0, l0, h1, l1;
    split2(v.x, v.y, h0, l0);
    split2(v.z, v.w, h1, l1);
    reinterpret_cast<uint2*>(g_kihi)[idx] = make_uint2(h0, h1);
    reinterpret_cast<uint2*>(g_kilo)[idx] = make_uint2(l0, l1);
}

// ================= bf16 2-split GEMM (ldmatrix): C = A[M,K]*B[N,K]^T =================
#define GBK 32
#define ROWB 40
#define TILEB (128*ROWB)
#define STGB (4*TILEB)
#define GEMM_SMEMB (3*STGB*2)

__global__ __launch_bounds__(256) void gemm_bf16(
    const bf16* __restrict__ Ahi, const bf16* __restrict__ Alo,
    const bf16* __restrict__ Bhi, const bf16* __restrict__ Blo,
    float* __restrict__ C, bf16* __restrict__ Chi, bf16* __restrict__ Clo,
    int M, int N, int K)
{
    extern __shared__ bf16 sb[];
    const int tid = threadIdx.x;
    const int wid = tid >> 5, lane = tid & 31;
    const int m0 = blockIdx.y * 128, n0 = blockIdx.x * 128;
    const int wm = (wid >> 2) * 64, wn = (wid & 3) * 32;
    const int r = lane >> 2, c = lane & 3;
    const uint32_t sbase = smem_to_u32(sb);

    float acc[4][4][4];
    #pragma unroll
    for (int i = 0; i < 4; i++)
        #pragma unroll
        for (int j = 0; j < 4; j++)
            #pragma unroll
            for (int q = 0; q < 4; q++) acc[i][j][q] = 0.f;

    const bf16* mats[4] = { Ahi + (size_t)m0*K, Alo + (size_t)m0*K,
                            Bhi + (size_t)n0*K, Blo + (size_t)n0*K };
    int l_mat[8], l_row[8], l_ch[8];
    #pragma unroll
    for (int i = 0; i < 8; i++) {
        int id = i*256 + tid;
        l_mat[i] = id >> 9; l_row[i] = (id >> 2) & 127; l_ch[i] = id & 3;
    }

    #define G_ISSUE(kt) do { \
        int _s = (kt) % 3, _k0 = (kt) * GBK; \
        _Pragma("unroll") \
        for (int _i = 0; _i < 8; _i++) { \
            const bf16* _src = mats[l_mat[_i]] + (size_t)l_row[_i]*K + _k0 + l_ch[_i]*8; \
            uint32_t _dst = sbase + (uint32_t)(_s*STGB + l_mat[_i]*TILEB + l_row[_i]*ROWB + l_ch[_i]*8)*2; \
            CP_ASYNC16(_dst, _src); \
        } \
    } while (0)

    const int nK = K / GBK;
    G_ISSUE(0); CP_COMMIT();
    G_ISSUE(1); CP_COMMIT();

    // ldmatrix lane-address components
    const int aRow = lane & 15, aColOff = (lane >> 4) << 3;
    const int bRow = lane & 7, bColOff = ((lane >> 3) & 1) << 3, bBlk = lane >> 4;

    for (int kt = 0; kt < nK; kt++) {
        CP_WAIT1();
        __syncthreads();
        if (kt + 2 < nK) { G_ISSUE(kt + 2); }
        CP_COMMIT();

        uint32_t Sb = sbase + (uint32_t)((kt % 3) * STGB) * 2;
        uint32_t Ah = Sb, Al = Sb + TILEB*2, Bh = Sb + 2*TILEB*2, Bl = Sb + 3*TILEB*2;

        #pragma unroll
        for (int k16 = 0; k16 < GBK; k16 += 16) {
            uint32_t ah[4][4], al[4][4], bh[4][2], bl[4][2];
            #pragma unroll
            for (int mt = 0; mt < 4; mt++) {
                uint32_t off = (uint32_t)((wm + mt*16 + aRow)*ROWB + k16 + aColOff) * 2;
                LDMX4(ah[mt][0], ah[mt][1], ah[mt][2], ah[mt][3], Ah + off);
                LDMX4(al[mt][0], al[mt][1], al[mt][2], al[mt][3], Al + off);
            }
            #pragma unroll
            for (int p = 0; p < 2; p++) {
                uint32_t off = (uint32_t)((wn + (2*p + bBlk)*8 + bRow)*ROWB + k16 + bColOff) * 2;
                LDMX4(bh[2*p][0], bh[2*p][1], bh[2*p+1][0], bh[2*p+1][1], Bh + off);
                LDMX4(bl[2*p][0], bl[2*p][1], bl[2*p+1][0], bl[2*p+1][1], Bl + off);
            }
            #pragma unroll
            for (int mt = 0; mt < 4; mt++)
                #pragma unroll
                for (int nt = 0; nt < 4; nt++) {
                    MMA_BF16(acc[mt][nt], ah[mt], bh[nt]);
                    MMA_BF16(acc[mt][nt], ah[mt], bl[nt]);
                    MMA_BF16(acc[mt][nt], al[mt], bh[nt]);
                }
        }
    }
    if (Chi) {
        #pragma unroll
        for (int mt = 0; mt < 4; mt++) {
            int row = m0 + wm + mt*16 + r;
            #pragma unroll
            for (int nt = 0; nt < 4; nt++) {
                int col = n0 + wn + nt*8 + 2*c;
                uint32_t h, l;
                split2(acc[mt][nt][0], acc[mt][nt][1], h, l);
                *(uint32_t*)&Chi[(size_t)row*N + col] = h;
                *(uint32_t*)&Clo[(size_t)row*N + col] = l;
                split2(acc[mt][nt][2], acc[mt][nt][3], h, l);
                *(uint32_t*)&Chi[(size_t)(row+8)*N + col] = h;
                *(uint32_t*)&Clo[(size_t)(row+8)*N + col] = l;
            }
        }
    } else {
        #pragma unroll
        for (int mt = 0; mt < 4; mt++) {
            int row = m0 + wm + mt*16 + r;
            #pragma unroll
            for (int nt = 0; nt < 4; nt++) {
                int col = n0 + wn + nt*8 + 2*c;
                *reinterpret_cast<float2*>(&C[(size_t)row*N + col]) = make_float2(acc[mt][nt][0], acc[mt][nt][1]);
                *reinterpret_cast<float2*>(&C[(size_t)(row+8)*N + col]) = make_float2(acc[mt][nt][2], acc[mt][nt][3]);
            }
        }
    }
}

// ================= tensor-core flash attention =================
#define ST 72
#define TB 9216
// smem bytes: quhi,qulo,qvhi,qvlo | phis,plos | khi2,klo2,vhi2,vlo2,rbhi2,rblo2 | bds | stats
#define O_QU 0
#define O_P  (4*TB)
#define O_KH (6*TB)
#define O_KL (8*TB)
#define O_VH (10*TB)
#define O_VL (12*TB)
#define O_RH (14*TB)
#define O_RL (16*TB)
#define O_BD (18*TB)
#define BDS 66
#define O_SMAX (O_BD + 2*64*BDS*4)
#define O_SSUM (O_SMAX + 512)
#define ATT_SMEM (O_SSUM + 512)

// BMODE 0: B row-major [n][k] (k,r). BMODE 1: B trans, stored [k][n] (v row-major)
template<int BMODE>
__device__ __forceinline__ void sgemm64(uint32_t Ah, uint32_t Al, uint32_t Bh, uint32_t Bl,
                                        int aro, int bro, int lane, float acc[4][4])
{
    const int aRow = lane & 15, aColOff = (lane >> 4) << 3;
    const int bRow = lane & 7, bHalf = (lane >> 3) & 1, bBlk = lane >> 4;
    #pragma unroll
    for (int kc = 0; kc < 4; kc++) {
        int co = kc * 16;
        uint32_t ah[4], al[4], bh[4][2], bl[4][2];
        uint32_t aoff = (uint32_t)((aro + aRow)*ST + co + aColOff) * 2;
        LDMX4(ah[0], ah[1], ah[2], ah[3], Ah + aoff);
        LDMX4(al[0], al[1], al[2], al[3], Al + aoff);
        #pragma unroll
        for (int p = 0; p < 2; p++) {
            uint32_t boff;
            if (BMODE == 0)
                boff = (uint32_t)((bro + (2*p + bBlk)*8 + bRow)*ST + co + bHalf*8) * 2;
            else
                boff = (uint32_t)((co + bRow + bHalf*8)*ST + bro + (2*p + bBlk)*8) * 2;
            if (BMODE == 0) {
                LDMX4(bh[2*p][0], bh[2*p][1], bh[2*p+1][0], bh[2*p+1][1], Bh + boff);
                LDMX4(bl[2*p][0], bl[2*p][1], bl[2*p+1][0], bl[2*p+1][1], Bl + boff);
            } else {
                LDMX4T(bh[2*p][0], bh[2*p][1], bh[2*p+1][0], bh[2*p+1][1], Bh + boff);
                LDMX4T(bl[2*p][0], bl[2*p][1], bl[2*p+1][0], bl[2*p+1][1], Bl + boff);
            }
        }
        #pragma unroll
        for (int nt = 0; nt < 4; nt++) {
            MMA_BF16(acc[nt], ah, bh[nt]);
            MMA_BF16(acc[nt], ah, bl[nt]);
            MMA_BF16(acc[nt], al, bh[nt]);
        }
    }
}

__global__ __launch_bounds__(256, 1) void attn_mma_kernel(
    const float* __restrict__ r_w_bias, const float* __restrict__ r_r_bias)
{
    extern __shared__ char smc[];
    const uint32_t sb = smem_to_u32(smc);
    float* bds  = (float*)(smc + O_BD);
    float* smax = (float*)(smc + O_SMAX);
    float* ssum = (float*)(smc + O_SSUM);

    const int tid = threadIdx.x;
    const int w = tid >> 5, lane = tid & 31;
    const int mt = w & 3, jh = w >> 2;
    const int r = lane >> 2, c = lane & 3;
    const int i0 = (15 - (int)blockIdx.x) * 64;
    const int b = blockIdx.y >> 4, hh = blockIdx.y & 15;
    const int lrow = tid >> 2;
    const int dseg = (tid & 3) * 16;         // 16 bf16 = 32B = 2 cp chunks
    const int aro = mt*16, bro = jh*32;
    const int relbase0 = 960 - i0;
    const int ntiles = i0/64 + 17;

    const size_t headoff = (size_t)hh*DH;

    // cp.async helpers (each thread: 2 chunks of one row)
    #define CP_TILE(dstoff, gptr) do { \
        uint32_t _d = sb + (uint32_t)(dstoff) + (uint32_t)(lrow*ST + dseg)*2; \
        const bf16* _s = (gptr) + dseg; \
        CP_ASYNC16(_d, _s); CP_ASYNC16(_d + 16, _s + 8); \
    } while (0)

    #define ISSUE_KV(kt, bufi) do { \
        size_t _row = (size_t)(b*KLEN + (kt)*64 + lrow)*DM + headoff; \
        CP_TILE(O_KH + (bufi)*TB, g_khi + _row); \
        CP_TILE(O_KL + (bufi)*TB, g_klo + _row); \
        CP_TILE(O_VH + (bufi)*TB, g_vhi + _row); \
        CP_TILE(O_VL + (bufi)*TB, g_vlo + _row); \
    } while (0)

    #define ISSUE_RB(band, bufi) do { \
        int _rel = relbase0 + (band)*64 + lrow; \
        _rel = _rel < 0 ? 0 : (_rel > KLEN-1 ? KLEN-1 : _rel); \
        size_t _row = (size_t)_rel*DM + headoff; \
        CP_TILE(O_RH + (bufi)*TB, g_rhi + _row); \
        CP_TILE(O_RL + (bufi)*TB, g_rlo + _row); \
    } while (0)

    // ---- q tile: f32 load, bias, scale, split ----
    {
        const float* qrow = g_q + ((size_t)(b*QLEN + i0 + lrow))*DM + headoff + dseg;
        const float* ub = r_w_bias + headoff + dseg;
        const float* vb = r_r_bias + headoff + dseg;
        bf16* quhi = (bf16*)(smc + O_QU);
        bf16* qulo = (bf16*)(smc + O_QU + TB);
        bf16* qvhi = (bf16*)(smc + O_QU + 2*TB);
        bf16* qvlo = (bf16*)(smc + O_QU + 3*TB);
        #pragma unroll
        for (int p = 0; p < 4; p++) {
            float4 q4 = reinterpret_cast<const float4*>(qrow)[p];
            float4 u4 = reinterpret_cast<const float4*>(ub)[p];
            float4 v4 = reinterpret_cast<const float4*>(vb)[p];
            int dd = dseg + p*4;
            uint32_t h, l;
            split2((q4.x+u4.x)*0.125f, (q4.y+u4.y)*0.125f, h, l);
            *(uint32_t*)&quhi[lrow*ST+dd] = h; *(uint32_t*)&qulo[lrow*ST+dd] = l;
            split2((q4.z+u4.z)*0.125f, (q4.w+u4.w)*0.125f, h, l);
            *(uint32_t*)&quhi[lrow*ST+dd+2] = h; *(uint32_t*)&qulo[lrow*ST+dd+2] = l;
            split2((q4.x+v4.x)*0.125f, (q4.y+v4.y)*0.125f, h, l);
            *(uint32_t*)&qvhi[lrow*ST+dd] = h; *(uint32_t*)&qvlo[lrow*ST+dd] = l;
            split2((q4.z+v4.z)*0.125f, (q4.w+v4.w)*0.125f, h, l);
            *(uint32_t*)&qvhi[lrow*ST+dd+2] = h; *(uint32_t*)&qvlo[lrow*ST+dd+2] = l;
        }
    }
    __syncthreads();

    const uint32_t sQU = sb + O_QU, sQV = sb + O_QU + 2*TB;
    const uint32_t sPH = sb + O_P, sPL = sb + O_P + TB;

    // ---- prologue BD bands 0,1 ----
    #pragma unroll
    for (int pre = 0; pre < 2; pre++) {
        ISSUE_RB(pre, pre);
        CP_COMMIT();
        CP_WAIT0();
        __syncthreads();
        float bda[4][4];
        #pragma unroll
        for (int nt = 0; nt < 4; nt++)
            #pragma unroll
            for (int q = 0; q < 4; q++) bda[nt][q] = 0.f;
        sgemm64<0>(sQV, sQV + TB, sb + O_RH + pre*TB, sb + O_RL + pre*TB, aro, bro, lane, bda);
        float* bdw = bds + pre * 64 * BDS;
        #pragma unroll
        for (int nt = 0; nt < 4; nt++) {
            int tc = bro + nt*8 + 2*c;
            *reinterpret_cast<float2*>(&bdw[(aro+r)*BDS + tc]) = make_float2(bda[nt][0], bda[nt][1]);
            *reinterpret_cast<float2*>(&bdw[(aro+r+8)*BDS + tc]) = make_float2(bda[nt][2], bda[nt][3]);
        }
        __syncthreads();   // rb buffer reuse safety
    }

    // ---- issue tile0 k/v + band2 ----
    ISSUE_KV(0, 0);
    ISSUE_RB(2, 0);
    CP_COMMIT();

    float out[4][4];
    #pragma unroll
    for (int nt = 0; nt < 4; nt++)
        #pragma unroll
        for (int q = 0; q < 4; q++) out[nt][q] = 0.f;
    float lsum0 = 0.f, lsum1 = 0.f, mrun0 = -1e30f, mrun1 = -1e30f;

    for (int kt = 0; kt < ntiles; kt++) {
        const int j0 = kt * 64;
        const int buf = kt & 1, nbuf = buf ^ 1;
        if (kt + 1 < ntiles) {
            ISSUE_KV(kt + 1, nbuf);
            ISSUE_RB(kt + 3, nbuf);
            CP_COMMIT();
            CP_WAIT1();
        } else {
            CP_WAIT0();
        }
        __syncthreads();

        // ---- AC ----
        float s[4][4];
        #pragma unroll
        for (int nt = 0; nt < 4; nt++)
            #pragma unroll
            for (int q = 0; q < 4; q++) s[nt][q] = 0.f;
        sgemm64<0>(sQU, sQU + TB, sb + O_KH + buf*TB, sb + O_KL + buf*TB, aro, bro, lane, s);

        // ---- BD gather + mask ----
        const float* bdLo = bds + buf * 64 * BDS;
        const float* bdHi = bds + nbuf * 64 * BDS;
        #pragma unroll
        for (int nt = 0; nt < 4; nt++)
            #pragma unroll
            for (int q = 0; q < 4; q++) {
                int il = aro + r + ((q >= 2) ? 8 : 0);
                int jl = bro + nt*8 + 2*c + (q & 1);
                int t = jl - il + 63;
                float bd = (t < 64) ? bdLo[il*BDS + t] : bdHi[il*BDS + t - 64];
                float sc = s[nt][q] + bd;
                if (j0 + jl > i0 + il + MLEN) sc = -1e30f;
                s[nt][q] = sc;
            }

        // ---- online softmax ----
        float pmax0 = -1e30f, pmax1 = -1e30f;
        #pragma unroll
        for (int nt = 0; nt < 4; nt++) {
            pmax0 = fmaxf(pmax0, fmaxf(s[nt][0], s[nt][1]));
            pmax1 = fmaxf(pmax1, fmaxf(s[nt][2], s[nt][3]));
        }
        pmax0 = fmaxf(pmax0, __shfl_xor_sync(~0u, pmax0, 1));
        pmax0 = fmaxf(pmax0, __shfl_xor_sync(~0u, pmax0, 2));
        pmax1 = fmaxf(pmax1, __shfl_xor_sync(~0u, pmax1, 1));
        pmax1 = fmaxf(pmax1, __shfl_xor_sync(~0u, pmax1, 2));
        if (c == 0) {
            smax[(aro+r)*2 + jh] = pmax0;
            smax[(aro+r+8)*2 + jh] = pmax1;
        }
        __syncthreads();
        float mn0 = fmaxf(mrun0, fmaxf(pmax0, smax[(aro+r)*2 + (1-jh)]));
        float mn1 = fmaxf(mrun1, fmaxf(pmax1, smax[(aro+r+8)*2 + (1-jh)]));

        float ps0 = 0.f, ps1 = 0.f;
        #pragma unroll
        for (int nt = 0; nt < 4; nt++) {
            s[nt][0] = __expf(s[nt][0] - mn0);
            s[nt][1] = __expf(s[nt][1] - mn0);
            s[nt][2] = __expf(s[nt][2] - mn1);
            s[nt][3] = __expf(s[nt][3] - mn1);
            ps0 += s[nt][0] + s[nt][1];
            ps1 += s[nt][2] + s[nt][3];
        }
        ps0 += __shfl_xor_sync(~0u, ps0, 1); ps0 += __shfl_xor_sync(~0u, ps0, 2);
        ps1 += __shfl_xor_sync(~0u, ps1, 1); ps1 += __shfl_xor_sync(~0u, ps1, 2);
        if (c == 0) {
            ssum[(aro+r)*2 + jh] = ps0;
            ssum[(aro+r+8)*2 + jh] = ps1;
        }
        bf16* phis = (bf16*)(smc + O_P);
        bf16* plos = (bf16*)(smc + O_P + TB);
        #pragma unroll
        for (int nt = 0; nt < 4; nt++) {
            int col = bro + nt*8 + 2*c;
            uint32_t h, l;
            split2(s[nt][0], s[nt][1], h, l);
            *(uint32_t*)&phis[(aro+r)*ST + col] = h;
            *(uint32_t*)&plos[(aro+r)*ST + col] = l;
            split2(s[nt][2], s[nt][3], h, l);
            *(uint32_t*)&phis[(aro+r+8)*ST + col] = h;
            *(uint32_t*)&plos[(aro+r+8)*ST + col] = l;
        }
        __syncthreads();
        float corr0 = __expf(mrun0 - mn0), corr1 = __expf(mrun1 - mn1);
        lsum0 = lsum0 * corr0 + ps0 + ssum[(aro+r)*2 + (1-jh)];
        lsum1 = lsum1 * corr1 + ps1 + ssum[(aro+r+8)*2 + (1-jh)];
        mrun0 = mn0; mrun1 = mn1;
        #pragma unroll
        for (int nt = 0; nt < 4; nt++) {
            out[nt][0] *= corr0; out[nt][1] *= corr0;
            out[nt][2] *= corr1; out[nt][3] *= corr1;
        }

        // ---- PV (V row-major, trans ldmatrix) ----
        sgemm64<1>(sPH, sPL, sb + O_VH + buf*TB, sb + O_VL + buf*TB, aro, bro, lane, out);

        // ---- next BD band ----
        if (kt + 1 < ntiles) {
            float bda[4][4];
            #pragma unroll
            for (int nt = 0; nt < 4; nt++)
                #pragma unroll
                for (int q = 0; q < 4; q++) bda[nt][q] = 0.f;
            sgemm64<0>(sQV, sQV + TB, sb + O_RH + buf*TB, sb + O_RL + buf*TB, aro, bro, lane, bda);
            float* bdw = bds + buf * 64 * BDS;
            #pragma unroll
            for (int nt = 0; nt < 4; nt++) {
                int tc = bro + nt*8 + 2*c;
                *reinterpret_cast<float2*>(&bdw[(aro+r)*BDS + tc]) = make_float2(bda[nt][0], bda[nt][1]);
                *reinterpret_cast<float2*>(&bdw[(aro+r+8)*BDS + tc]) = make_float2(bda[nt][2], bda[nt][3]);
            }
        }
        __syncthreads();  // buffer reuse safety before next issue
    }

    // ---- epilogue ----
    float inv0 = 1.f / lsum0, inv1 = 1.f / lsum1;
    #pragma unroll
    for (int nt = 0; nt < 4; nt++) {
        int col = hh*DH + bro + nt*8 + 2*c;
        size_t row0 = (size_t)(b*QLEN + i0 + aro + r) * DM + col;
        size_t row1 = row0 + 8*DM;
        uint32_t h, l;
        split2(out[nt][0]*inv0, out[nt][1]*inv0, h, l);
        *(uint32_t*)&g_avhi[row0] = h; *(uint32_t*)&g_avlo[row0] = l;
        split2(out[nt][2]*inv1, out[nt][3]*inv1, h, l);
        *(uint32_t*)&g_avhi[row1] = h; *(uint32_t*)&g_avlo[row1] = l;
    }
}

// ---------------- launch ----------------
extern "C" void kernel_launch(void* const* d_in, const int* in_sizes, int n_in,
                              void* d_out, int out_size)
{
    (void)in_sizes; (void)n_in; (void)out_size;
    const float* x   = (const float*)d_in[0];
    const float* mem = (const float*)d_in[1];
    const float* pos = (const float*)d_in[2];
    const float* Wq  = (const float*)d_in[4];
    const float* Wk  = (const float*)d_in[5];
    const float* Wv  = (const float*)d_in[6];
    const float* Wr  = (const float*)d_in[7];
    const float* Wo  = (const float*)d_in[8];
    const float* rwb = (const float*)d_in[9];
    const float* rrb = (const float*)d_in[10];
    float* out = (float*)d_out;

    float *pq;
    bf16 *pkh, *pkl, *pvh, *pvl, *prh, *prl;
    bf16 *pxh, *pxl, *pkih, *pkil, *pph, *ppl, *pwh, *pwl, *pavh, *pavl;
    cudaGetSymbolAddress((void**)&pq,   g_q);
    cudaGetSymbolAddress((void**)&pkh,  g_khi);
    cudaGetSymbolAddress((void**)&pkl,  g_klo);
    cudaGetSymbolAddress((void**)&pvh,  g_vhi);
    cudaGetSymbolAddress((void**)&pvl,  g_vlo);
    cudaGetSymbolAddress((void**)&prh,  g_rhi);
    cudaGetSymbolAddress((void**)&prl,  g_rlo);
    cudaGetSymbolAddress((void**)&pxh,  g_xhi);
    cudaGetSymbolAddress((void**)&pxl,  g_xlo);
    cudaGetSymbolAddress((void**)&pkih, g_kihi);
    cudaGetSymbolAddress((void**)&pkil, g_kilo);
    cudaGetSymbolAddress((void**)&pph,  g_pohi);
    cudaGetSymbolAddress((void**)&ppl,  g_polo);
    cudaGetSymbolAddress((void**)&pwh,  g_whi);
    cudaGetSymbolAddress((void**)&pwl,  g_wlo);
    cudaGetSymbolAddress((void**)&pavh, g_avhi);
    cudaGetSymbolAddress((void**)&pavl, g_avlo);

    const int WN = DM*DM;
    split_kernel<<<(BSZ*QLEN*DM/4 + 255)/256, 256>>>(x,   pxh, pxl, BSZ*QLEN*DM/4);
    split_kernel<<<(KLEN*DM/4 + 255)/256, 256>>>(pos, pph, ppl, KLEN*DM/4);
    split_kernel<<<(WN/4 + 255)/256, 256>>>(Wq, pwh + 0*WN, pwl + 0*WN, WN/4);
    split_kernel<<<(WN/4 + 255)/256, 256>>>(Wk, pwh + 1*WN, pwl + 1*WN, WN/4);
    split_kernel<<<(WN/4 + 255)/256, 256>>>(Wv, pwh + 2*WN, pwl + 2*WN, WN/4);
    split_kernel<<<(WN/4 + 255)/256, 256>>>(Wr, pwh + 3*WN, pwl + 3*WN, WN/4);
    split_kernel<<<(WN/4 + 255)/256, 256>>>(Wo, pwh + 4*WN, pwl + 4*WN, WN/4);
    concat_split_kernel<<<(BSZ*KLEN*DM/4 + 255)/256, 256>>>(mem, x);

    cudaFuncSetAttribute(gemm_bf16, cudaFuncAttributeMaxDynamicSharedMemorySize, GEMM_SMEMB);
    gemm_bf16<<<dim3(DM/128, BSZ*QLEN/128), 256, GEMM_SMEMB>>>(pxh, pxl, pwh+0*WN, pwl+0*WN, pq, nullptr, nullptr, BSZ*QLEN, DM, DM);
    gemm_bf16<<<dim3(DM/128, BSZ*KLEN/128), 256, GEMM_SMEMB>>>(pkih, pkil, pwh+1*WN, pwl+1*WN, nullptr, pkh, pkl, BSZ*KLEN, DM, DM);
    gemm_bf16<<<dim3(DM/128, BSZ*KLEN/128), 256, GEMM_SMEMB>>>(pkih, pkil, pwh+2*WN, pwl+2*WN, nullptr, pvh, pvl, BSZ*KLEN, DM, DM);
    gemm_bf16<<<dim3(DM/128, KLEN/128),     256, GEMM_SMEMB>>>(pph, ppl, pwh+3*WN, pwl+3*WN, nullptr, prh, prl, KLEN, DM, DM);

    cudaFuncSetAttribute(attn_mma_kernel, cudaFuncAttributeMaxDynamicSharedMemorySize, ATT_SMEM);
    attn_mma_kernel<<<dim3(QLEN/64, BSZ*NH), 256, ATT_SMEM>>>(rwb, rrb);

    gemm_bf16<<<dim3(DM/128, BSZ*QLEN/128), 256, GEMM_SMEMB>>>(pavh, pavl, pwh+4*WN, pwl+4*WN, out, nullptr, nullptr, BSZ*QLEN, DM, DM);
}

// round 8
// speedup vs baseline: 2.9381x; 1.0624x over previous
#include <cuda_runtime.h>
#include <cuda_bf16.h>
#include <cstdint>
#include <math.h>

#define BSZ 2
#define QLEN 1024
#define MLEN 1024
#define KLEN 2048
#define NH 16
#define DH 64
#define DM 1024

typedef __nv_bfloat16 bf16;
typedef __nv_bfloat162 bf162;

// ---------------- scratch ----------------
__device__ float g_q  [BSZ*QLEN*DM];
__device__ bf16 g_khi [BSZ*KLEN*DM];
__device__ bf16 g_klo [BSZ*KLEN*DM];
__device__ bf16 g_vhi [BSZ*KLEN*DM];
__device__ bf16 g_vlo [BSZ*KLEN*DM];
__device__ bf16 g_rhi [KLEN*DM];
__device__ bf16 g_rlo [KLEN*DM];
__device__ bf16 g_xhi [BSZ*QLEN*DM];
__device__ bf16 g_xlo [BSZ*QLEN*DM];
__device__ bf16 g_kihi[BSZ*KLEN*DM];
__device__ bf16 g_kilo[BSZ*KLEN*DM];
__device__ bf16 g_pohi[KLEN*DM];
__device__ bf16 g_polo[KLEN*DM];
__device__ bf16 g_whi [5*DM*DM];
__device__ bf16 g_wlo [5*DM*DM];
__device__ bf16 g_avhi[BSZ*QLEN*DM];
__device__ bf16 g_avlo[BSZ*QLEN*DM];

// ---------------- helpers ----------------
__device__ __forceinline__ uint32_t smem_to_u32(const void* p) {
    uint32_t a;
    asm("{ .reg .u64 t; cvta.to.shared.u64 t, %1; cvt.u32.u64 %0, t; }" : "=r"(a) : "l"(p));
    return a;
}
#define CP_ASYNC16(dst, src) \
    asm volatile("cp.async.cg.shared.global [%0], [%1], 16;" :: "r"(dst), "l"(src) : "memory")
#define CP_COMMIT() asm volatile("cp.async.commit_group;" ::: "memory")
#define CP_WAIT1()  asm volatile("cp.async.wait_group 1;" ::: "memory")
#define CP_WAIT0()  asm volatile("cp.async.wait_group 0;" ::: "memory")

#define MMA_BF16(d, a, b) \
    asm volatile("mma.sync.aligned.m16n8k16.row.col.f32.bf16.bf16.f32 " \
        "{%0,%1,%2,%3}, {%4,%5,%6,%7}, {%8,%9}, {%0,%1,%2,%3};" \
        : "+f"((d)[0]), "+f"((d)[1]), "+f"((d)[2]), "+f"((d)[3]) \
        : "r"((a)[0]), "r"((a)[1]), "r"((a)[2]), "r"((a)[3]), \
          "r"((b)[0]), "r"((b)[1]))

#define LDMX4(r0, r1, r2, r3, addr) \
    asm volatile("ldmatrix.sync.aligned.m8n8.x4.shared.b16 {%0,%1,%2,%3}, [%4];" \
        : "=r"(r0), "=r"(r1), "=r"(r2), "=r"(r3) : "r"(addr))
#define LDMX4T(r0, r1, r2, r3, addr) \
    asm volatile("ldmatrix.sync.aligned.m8n8.x4.trans.shared.b16 {%0,%1,%2,%3}, [%4];" \
        : "=r"(r0), "=r"(r1), "=r"(r2), "=r"(r3) : "r"(addr))

__device__ __forceinline__ void split2(float a, float b, uint32_t& hi, uint32_t& lo) {
    bf162 h = __floats2bfloat162_rn(a, b);
    bf162 l = __floats2bfloat162_rn(a - __bfloat162float(h.x), b - __bfloat162float(h.y));
    hi = *reinterpret_cast<uint32_t*>(&h);
    lo = *reinterpret_cast<uint32_t*>(&l);
}

// ---------------- prep (fused): split x, pos, 5 weights ----------------
#define XN4 (BSZ*QLEN*DM/4)
#define PN4 (KLEN*DM/4)
#define WN4 (DM*DM/4)
#define PREP_TOT (XN4 + PN4 + 5*WN4)

__global__ void prep_split(const float* __restrict__ x, const float* __restrict__ pos,
                           const float* __restrict__ Wq, const float* __restrict__ Wk,
                           const float* __restrict__ Wv, const float* __restrict__ Wr,
                           const float* __restrict__ Wo) {
    int idx = blockIdx.x * blockDim.x + threadIdx.x;
    if (idx >= PREP_TOT) return;
    const float* src; bf16 *hi, *lo; int base;
    if (idx < XN4)                { src = x;  hi = g_xhi; lo = g_xlo; base = 0; }
    else if (idx < XN4+PN4)       { src = pos; hi = g_pohi; lo = g_polo; base = XN4; }
    else if (idx < XN4+PN4+WN4)   { src = Wq; hi = g_whi;        lo = g_wlo;        base = XN4+PN4; }
    else if (idx < XN4+PN4+2*WN4) { src = Wk; hi = g_whi+DM*DM;  lo = g_wlo+DM*DM;  base = XN4+PN4+WN4; }
    else if (idx < XN4+PN4+3*WN4) { src = Wv; hi = g_whi+2*DM*DM; lo = g_wlo+2*DM*DM; base = XN4+PN4+2*WN4; }
    else if (idx < XN4+PN4+4*WN4) { src = Wr; hi = g_whi+3*DM*DM; lo = g_wlo+3*DM*DM; base = XN4+PN4+3*WN4; }
    else                          { src = Wo; hi = g_whi+4*DM*DM; lo = g_wlo+4*DM*DM; base = XN4+PN4+4*WN4; }
    int i = idx - base;
    float4 v = reinterpret_cast<const float4*>(src)[i];
    uint32_t h0, l0, h1, l1;
    split2(v.x, v.y, h0, l0);
    split2(v.z, v.w, h1, l1);
    reinterpret_cast<uint2*>(hi)[i] = make_uint2(h0, h1);
    reinterpret_cast<uint2*>(lo)[i] = make_uint2(l0, l1);
}

__global__ void concat_split_kernel(const float* __restrict__ mem, const float* __restrict__ x) {
    int idx = blockIdx.x * blockDim.x + threadIdx.x;
    if (idx >= BSZ*KLEN*DM/4) return;
    int e4   = idx & (DM/4 - 1);
    int rest = idx / (DM/4);
    int j = rest & (KLEN - 1);
    int b = rest >> 11;
    float4 v;
    if (j < MLEN) v = reinterpret_cast<const float4*>(mem)[(b*MLEN + j)*(DM/4) + e4];
    else          v = reinterpret_cast<const float4*>(x)[(b*QLEN + (j - MLEN))*(DM/4) + e4];
    uint32_t h0, l0, h1, l1;
    split2(v.x, v.y, h0, l0);
    split2(v.z, v.w, h1, l1);
    reinterpret_cast<uint2*>(g_kihi)[idx] = make_uint2(h0, h1);
    reinterpret_cast<uint2*>(g_kilo)[idx] = make_uint2(l0, l1);
}

// ================= bf16 2-split GEMM body =================
#define GBK 32
#define ROWB 40
#define TILEB (128*ROWB)
#define STGB (4*TILEB)
#define GEMM_SMEMB (3*STGB*2)

__device__ __forceinline__ void gemm_body(
    const bf16* __restrict__ Ahi, const bf16* __restrict__ Alo,
    const bf16* __restrict__ Bhi, const bf16* __restrict__ Blo,
    float* __restrict__ C, bf16* __restrict__ Chi, bf16* __restrict__ Clo,
    int m0, int n0, int N, int K)
{
    extern __shared__ bf16 sb[];
    const int tid = threadIdx.x;
    const int wid = tid >> 5, lane = tid & 31;
    const int wm = (wid >> 2) * 64, wn = (wid & 3) * 32;
    const int r = lane >> 2, c = lane & 3;
    const uint32_t sbase = smem_to_u32(sb);

    float acc[4][4][4];
    #pragma unroll
    for (int i = 0; i < 4; i++)
        #pragma unroll
        for (int j = 0; j < 4; j++)
            #pragma unroll
            for (int q = 0; q < 4; q++) acc[i][j][q] = 0.f;

    const bf16* mats[4] = { Ahi + (size_t)m0*K, Alo + (size_t)m0*K,
                            Bhi + (size_t)n0*K, Blo + (size_t)n0*K };
    int l_mat[8], l_row[8], l_ch[8];
    #pragma unroll
    for (int i = 0; i < 8; i++) {
        int id = i*256 + tid;
        l_mat[i] = id >> 9; l_row[i] = (id >> 2) & 127; l_ch[i] = id & 3;
    }

    #define G_ISSUE(kt) do { \
        int _s = (kt) % 3, _k0 = (kt) * GBK; \
        _Pragma("unroll") \
        for (int _i = 0; _i < 8; _i++) { \
            const bf16* _src = mats[l_mat[_i]] + (size_t)l_row[_i]*K + _k0 + l_ch[_i]*8; \
            uint32_t _dst = sbase + (uint32_t)(_s*STGB + l_mat[_i]*TILEB + l_row[_i]*ROWB + l_ch[_i]*8)*2; \
            CP_ASYNC16(_dst, _src); \
        } \
    } while (0)

    const int nK = K / GBK;
    G_ISSUE(0); CP_COMMIT();
    G_ISSUE(1); CP_COMMIT();

    const int aRow = lane & 15, aColOff = (lane >> 4) << 3;
    const int bRow = lane & 7, bColOff = ((lane >> 3) & 1) << 3, bBlk = lane >> 4;

    for (int kt = 0; kt < nK; kt++) {
        CP_WAIT1();
        __syncthreads();
        if (kt + 2 < nK) { G_ISSUE(kt + 2); }
        CP_COMMIT();

        uint32_t Sb = sbase + (uint32_t)((kt % 3) * STGB) * 2;
        uint32_t Ah = Sb, Al = Sb + TILEB*2, Bh = Sb + 2*TILEB*2, Bl = Sb + 3*TILEB*2;

        #pragma unroll
        for (int k16 = 0; k16 < GBK; k16 += 16) {
            uint32_t ah[4][4], al[4][4], bh[4][2], bl[4][2];
            #pragma unroll
            for (int mt = 0; mt < 4; mt++) {
                uint32_t off = (uint32_t)((wm + mt*16 + aRow)*ROWB + k16 + aColOff) * 2;
                LDMX4(ah[mt][0], ah[mt][1], ah[mt][2], ah[mt][3], Ah + off);
                LDMX4(al[mt][0], al[mt][1], al[mt][2], al[mt][3], Al + off);
            }
            #pragma unroll
            for (int p = 0; p < 2; p++) {
                uint32_t off = (uint32_t)((wn + (2*p + bBlk)*8 + bRow)*ROWB + k16 + bColOff) * 2;
                LDMX4(bh[2*p][0], bh[2*p][1], bh[2*p+1][0], bh[2*p+1][1], Bh + off);
                LDMX4(bl[2*p][0], bl[2*p][1], bl[2*p+1][0], bl[2*p+1][1], Bl + off);
            }
            #pragma unroll
            for (int mt = 0; mt < 4; mt++)
                #pragma unroll
                for (int nt = 0; nt < 4; nt++) {
                    MMA_BF16(acc[mt][nt], ah[mt], bh[nt]);
                    MMA_BF16(acc[mt][nt], ah[mt], bl[nt]);
                    MMA_BF16(acc[mt][nt], al[mt], bh[nt]);
                }
        }
    }
    if (Chi) {
        #pragma unroll
        for (int mt = 0; mt < 4; mt++) {
            int row = m0 + wm + mt*16 + r;
            #pragma unroll
            for (int nt = 0; nt < 4; nt++) {
                int col = n0 + wn + nt*8 + 2*c;
                uint32_t h, l;
                split2(acc[mt][nt][0], acc[mt][nt][1], h, l);
                *(uint32_t*)&Chi[(size_t)row*N + col] = h;
                *(uint32_t*)&Clo[(size_t)row*N + col] = l;
                split2(acc[mt][nt][2], acc[mt][nt][3], h, l);
                *(uint32_t*)&Chi[(size_t)(row+8)*N + col] = h;
                *(uint32_t*)&Clo[(size_t)(row+8)*N + col] = l;
            }
        }
    } else {
        #pragma unroll
        for (int mt = 0; mt < 4; mt++) {
            int row = m0 + wm + mt*16 + r;
            #pragma unroll
            for (int nt = 0; nt < 4; nt++) {
                int col = n0 + wn + nt*8 + 2*c;
                *reinterpret_cast<float2*>(&C[(size_t)row*N + col]) = make_float2(acc[mt][nt][0], acc[mt][nt][1]);
                *reinterpret_cast<float2*>(&C[(size_t)(row+8)*N + col]) = make_float2(acc[mt][nt][2], acc[mt][nt][3]);
            }
        }
    }
}

// fused projection GEMMs: q | k | v | r (grid.y = 16+32+32+16)
__global__ __launch_bounds__(256) void gemm_proj4() {
    int y = blockIdx.y;
    const int WN = DM*DM;
    if (y < 16)
        gemm_body(g_xhi, g_xlo, g_whi, g_wlo, g_q, nullptr, nullptr, y*128, blockIdx.x*128, DM, DM);
    else if (y < 48)
        gemm_body(g_kihi, g_kilo, g_whi+WN, g_wlo+WN, nullptr, g_khi, g_klo, (y-16)*128, blockIdx.x*128, DM, DM);
    else if (y < 80)
        gemm_body(g_kihi, g_kilo, g_whi+2*WN, g_wlo+2*WN, nullptr, g_vhi, g_vlo, (y-48)*128, blockIdx.x*128, DM, DM);
    else
        gemm_body(g_pohi, g_polo, g_whi+3*WN, g_wlo+3*WN, nullptr, g_rhi, g_rlo, (y-80)*128, blockIdx.x*128, DM, DM);
}

__global__ __launch_bounds__(256) void gemm_bf16(
    const bf16* __restrict__ Ahi, const bf16* __restrict__ Alo,
    const bf16* __restrict__ Bhi, const bf16* __restrict__ Blo,
    float* __restrict__ C, int M, int N, int K)
{
    gemm_body(Ahi, Alo, Bhi, Blo, C, nullptr, nullptr, blockIdx.y*128, blockIdx.x*128, N, K);
}

// ================= tensor-core flash attention (P in registers) =================
#define ST 72
#define TB 9216
#define O_QU 0
#define O_KH (4*TB)
#define O_KL (6*TB)
#define O_VH (8*TB)
#define O_VL (10*TB)
#define O_RH (12*TB)
#define O_RL (14*TB)
#define O_BD (16*TB)
#define BDS 66
#define O_ST (O_BD + 2*64*BDS*4)
#define ATT_SMEM (O_ST + 1024)
#define REDS 66

__global__ __launch_bounds__(256, 1) void attn_mma_kernel(
    const float* __restrict__ r_w_bias, const float* __restrict__ r_r_bias)
{
    extern __shared__ char smc[];
    const uint32_t sb = smem_to_u32(smc);
    float* bds  = (float*)(smc + O_BD);
    float* mred = (float*)(smc + O_ST);
    float* lred = mred + 64;

    const int tid = threadIdx.x;
    const int w = tid >> 5, lane = tid & 31;
    const int mt = w & 3, jh = w >> 2;
    const int r = lane >> 2, c = lane & 3;
    const int i0 = (15 - (int)blockIdx.x) * 64;
    const int b = blockIdx.y >> 4, hh = blockIdx.y & 15;
    const int lrow = tid >> 2;
    const int dseg = (tid & 3) * 16;
    const int aro = mt*16, bro = jh*32;
    const int relbase0 = 960 - i0;
    const int ntiles = i0/64 + 17;
    const size_t headoff = (size_t)hh*DH;

    const int aRow = lane & 15, aColOff = (lane >> 4) << 3;
    const int bRow = lane & 7, bHalf = (lane >> 3) & 1, bBlk = lane >> 4;

    #define CP_TILE(dstoff, gptr) do { \
        uint32_t _d = sb + (uint32_t)(dstoff) + (uint32_t)(lrow*ST + dseg)*2; \
        const bf16* _s = (gptr) + dseg; \
        CP_ASYNC16(_d, _s); CP_ASYNC16(_d + 16, _s + 8); \
    } while (0)
    #define ISSUE_KV(kt, bufi) do { \
        size_t _row = (size_t)(b*KLEN + (kt)*64 + lrow)*DM + headoff; \
        CP_TILE(O_KH + (bufi)*TB, g_khi + _row); \
        CP_TILE(O_KL + (bufi)*TB, g_klo + _row); \
        CP_TILE(O_VH + (bufi)*TB, g_vhi + _row); \
        CP_TILE(O_VL + (bufi)*TB, g_vlo + _row); \
    } while (0)
    #define ISSUE_RB(band, bufi) do { \
        int _rel = relbase0 + (band)*64 + lrow; \
        _rel = _rel < 0 ? 0 : (_rel > KLEN-1 ? KLEN-1 : _rel); \
        size_t _row = (size_t)_rel*DM + headoff; \
        CP_TILE(O_RH + (bufi)*TB, g_rhi + _row); \
        CP_TILE(O_RL + (bufi)*TB, g_rlo + _row); \
    } while (0)

    ISSUE_RB(0, 0); CP_COMMIT();
    ISSUE_RB(1, 1); ISSUE_KV(0, 0); CP_COMMIT();

    // ---- q prep into smem ----
    {
        const float* qrow = g_q + ((size_t)(b*QLEN + i0 + lrow))*DM + headoff + dseg;
        const float* ub = r_w_bias + headoff + dseg;
        const float* vb = r_r_bias + headoff + dseg;
        bf16* quhi = (bf16*)(smc + O_QU);
        bf16* qulo = (bf16*)(smc + O_QU + TB);
        bf16* qvhi = (bf16*)(smc + O_QU + 2*TB);
        bf16* qvlo = (bf16*)(smc + O_QU + 3*TB);
        #pragma unroll
        for (int p = 0; p < 4; p++) {
            float4 q4 = reinterpret_cast<const float4*>(qrow)[p];
            float4 u4 = reinterpret_cast<const float4*>(ub)[p];
            float4 v4 = reinterpret_cast<const float4*>(vb)[p];
            int dd = dseg + p*4;
            uint32_t h, l;
            split2((q4.x+u4.x)*0.125f, (q4.y+u4.y)*0.125f, h, l);
            *(uint32_t*)&quhi[lrow*ST+dd] = h; *(uint32_t*)&qulo[lrow*ST+dd] = l;
            split2((q4.z+u4.z)*0.125f, (q4.w+u4.w)*0.125f, h, l);
            *(uint32_t*)&quhi[lrow*ST+dd+2] = h; *(uint32_t*)&qulo[lrow*ST+dd+2] = l;
            split2((q4.x+v4.x)*0.125f, (q4.y+v4.y)*0.125f, h, l);
            *(uint32_t*)&qvhi[lrow*ST+dd] = h; *(uint32_t*)&qvlo[lrow*ST+dd] = l;
            split2((q4.z+v4.z)*0.125f, (q4.w+v4.w)*0.125f, h, l);
            *(uint32_t*)&qvhi[lrow*ST+dd+2] = h; *(uint32_t*)&qvlo[lrow*ST+dd+2] = l;
        }
    }
    CP_WAIT1();            // rb0 ready
    __syncthreads();       // + q stores visible

    // ---- preload q fragments ----
    uint32_t quh[4][4], qul[4][4], qvh[4][4], qvl[4][4];
    #pragma unroll
    for (int kc = 0; kc < 4; kc++) {
        uint32_t aoff = (uint32_t)((aro + aRow)*ST + kc*16 + aColOff) * 2;
        LDMX4(quh[kc][0], quh[kc][1], quh[kc][2], quh[kc][3], sb + O_QU + aoff);
        LDMX4(qul[kc][0], qul[kc][1], qul[kc][2], qul[kc][3], sb + O_QU + TB + aoff);
        LDMX4(qvh[kc][0], qvh[kc][1], qvh[kc][2], qvh[kc][3], sb + O_QU + 2*TB + aoff);
        LDMX4(qvl[kc][0], qvl[kc][1], qvl[kc][2], qvl[kc][3], sb + O_QU + 3*TB + aoff);
    }

    // 64x32 GEMM with preloaded A frags, B row-major [n][k] in smem
    #define GEMM_NK(ACC, AH, AL, BHbase, BLbase) do { \
        _Pragma("unroll") \
        for (int kc = 0; kc < 4; kc++) { \
            uint32_t bh[4][2], bl[4][2]; \
            _Pragma("unroll") \
            for (int p = 0; p < 2; p++) { \
                uint32_t boff = (uint32_t)((bro + (2*p + bBlk)*8 + bRow)*ST + kc*16 + bHalf*8) * 2; \
                LDMX4(bh[2*p][0], bh[2*p][1], bh[2*p+1][0], bh[2*p+1][1], (BHbase) + boff); \
                LDMX4(bl[2*p][0], bl[2*p][1], bl[2*p+1][0], bl[2*p+1][1], (BLbase) + boff); \
            } \
            _Pragma("unroll") \
            for (int nt = 0; nt < 4; nt++) { \
                MMA_BF16(ACC[nt], AH[kc], bh[nt]); \
                MMA_BF16(ACC[nt], AH[kc], bl[nt]); \
                MMA_BF16(ACC[nt], AL[kc], bh[nt]); \
            } \
        } \
    } while (0)

    // ---- prologue BD bands 0,1 ----
    {
        float bda[4][4];
        #pragma unroll
        for (int nt = 0; nt < 4; nt++)
            #pragma unroll
            for (int q = 0; q < 4; q++) bda[nt][q] = 0.f;
        GEMM_NK(bda, qvh, qvl, sb + O_RH, sb + O_RL);
        float* bdw = bds;
        #pragma unroll
        for (int nt = 0; nt < 4; nt++) {
            int tc = bro + nt*8 + 2*c;
            *reinterpret_cast<float2*>(&bdw[(aro+r)*BDS + tc]) = make_float2(bda[nt][0], bda[nt][1]);
            *reinterpret_cast<float2*>(&bdw[(aro+r+8)*BDS + tc]) = make_float2(bda[nt][2], bda[nt][3]);
        }
    }
    __syncthreads();                 // rbuf0 free
    ISSUE_RB(2, 0); CP_COMMIT();
    CP_WAIT1();                      // rb1 + kv0 ready
    __syncthreads();
    {
        float bda[4][4];
        #pragma unroll
        for (int nt = 0; nt < 4; nt++)
            #pragma unroll
            for (int q = 0; q < 4; q++) bda[nt][q] = 0.f;
        GEMM_NK(bda, qvh, qvl, sb + O_RH + TB, sb + O_RL + TB);
        float* bdw = bds + 64*BDS;
        #pragma unroll
        for (int nt = 0; nt < 4; nt++) {
            int tc = bro + nt*8 + 2*c;
            *reinterpret_cast<float2*>(&bdw[(aro+r)*BDS + tc]) = make_float2(bda[nt][0], bda[nt][1]);
            *reinterpret_cast<float2*>(&bdw[(aro+r+8)*BDS + tc]) = make_float2(bda[nt][2], bda[nt][3]);
        }
    }

    float out[8][4];
    #pragma unroll
    for (int nt = 0; nt < 8; nt++)
        #pragma unroll
        for (int q = 0; q < 4; q++) out[nt][q] = 0.f;
    float lsum0 = 0.f, lsum1 = 0.f, mrun0 = -1e4f, mrun1 = -1e4f;

    for (int kt = 0; kt < ntiles; kt++) {
        const int j0 = kt * 64;
        const int buf = kt & 1, nbuf = buf ^ 1;
        CP_WAIT0();
        __syncthreads();
        if (kt + 1 < ntiles) {
            ISSUE_KV(kt + 1, nbuf);
            ISSUE_RB(kt + 3, nbuf);
            CP_COMMIT();
        }

        // ---- AC ----
        float s[4][4];
        #pragma unroll
        for (int nt = 0; nt < 4; nt++)
            #pragma unroll
            for (int q = 0; q < 4; q++) s[nt][q] = 0.f;
        GEMM_NK(s, quh, qul, sb + O_KH + buf*TB, sb + O_KL + buf*TB);

        // ---- BD gather + mask ----
        const float* bdLo = bds + buf * 64 * BDS;
        const float* bdHi = bds + nbuf * 64 * BDS;
        #pragma unroll
        for (int nt = 0; nt < 4; nt++)
            #pragma unroll
            for (int q = 0; q < 4; q++) {
                int il = aro + r + ((q >= 2) ? 8 : 0);
                int jl = bro + nt*8 + 2*c + (q & 1);
                int t = jl - il + 63;
                float bd = (t < 64) ? bdLo[il*BDS + t] : bdHi[il*BDS + t - 64];
                float sc = s[nt][q] + bd;
                if (j0 + jl > i0 + il + MLEN) sc = -1e30f;
                s[nt][q] = sc;
            }

        // ---- per-half online softmax ----
        float pmax0 = -1e30f, pmax1 = -1e30f;
        #pragma unroll
        for (int nt = 0; nt < 4; nt++) {
            pmax0 = fmaxf(pmax0, fmaxf(s[nt][0], s[nt][1]));
            pmax1 = fmaxf(pmax1, fmaxf(s[nt][2], s[nt][3]));
        }
        pmax0 = fmaxf(pmax0, __shfl_xor_sync(~0u, pmax0, 1));
        pmax0 = fmaxf(pmax0, __shfl_xor_sync(~0u, pmax0, 2));
        pmax1 = fmaxf(pmax1, __shfl_xor_sync(~0u, pmax1, 1));
        pmax1 = fmaxf(pmax1, __shfl_xor_sync(~0u, pmax1, 2));
        float mn0 = fmaxf(mrun0, pmax0), mn1 = fmaxf(mrun1, pmax1);
        float ps0 = 0.f, ps1 = 0.f;
        #pragma unroll
        for (int nt = 0; nt < 4; nt++) {
            s[nt][0] = __expf(s[nt][0] - mn0);
            s[nt][1] = __expf(s[nt][1] - mn0);
            s[nt][2] = __expf(s[nt][2] - mn1);
            s[nt][3] = __expf(s[nt][3] - mn1);
            ps0 += s[nt][0] + s[nt][1];
            ps1 += s[nt][2] + s[nt][3];
        }
        ps0 += __shfl_xor_sync(~0u, ps0, 1); ps0 += __shfl_xor_sync(~0u, ps0, 2);
        ps1 += __shfl_xor_sync(~0u, ps1, 1); ps1 += __shfl_xor_sync(~0u, ps1, 2);
        float corr0 = __expf(mrun0 - mn0), corr1 = __expf(mrun1 - mn1);
        lsum0 = lsum0 * corr0 + ps0;
        lsum1 = lsum1 * corr1 + ps1;
        mrun0 = mn0; mrun1 = mn1;
        #pragma unroll
        for (int nt = 0; nt < 8; nt++) {
            out[nt][0] *= corr0; out[nt][1] *= corr0;
            out[nt][2] *= corr1; out[nt][3] *= corr1;
        }

        // ---- pack P A-frags from registers ----
        uint32_t pah[2][4], pal[2][4];
        #pragma unroll
        for (int kc = 0; kc < 2; kc++) {
            split2(s[2*kc][0],   s[2*kc][1],   pah[kc][0], pal[kc][0]);
            split2(s[2*kc][2],   s[2*kc][3],   pah[kc][1], pal[kc][1]);
            split2(s[2*kc+1][0], s[2*kc+1][1], pah[kc][2], pal[kc][2]);
            split2(s[2*kc+1][2], s[2*kc+1][3], pah[kc][3], pal[kc][3]);
        }

        // ---- PV: out += P(16 x 32own) @ V(32own x 64) ----
        {
            uint32_t VH = sb + O_VH + buf*TB, VL = sb + O_VL + buf*TB;
            #pragma unroll
            for (int kc = 0; kc < 2; kc++) {
                int co = jh*32 + kc*16;
                uint32_t vh[8][2], vl[8][2];
                #pragma unroll
                for (int p = 0; p < 4; p++) {
                    uint32_t boff = (uint32_t)((co + bRow + bHalf*8)*ST + (2*p + bBlk)*8) * 2;
                    LDMX4T(vh[2*p][0], vh[2*p][1], vh[2*p+1][0], vh[2*p+1][1], VH + boff);
                    LDMX4T(vl[2*p][0], vl[2*p][1], vl[2*p+1][0], vl[2*p+1][1], VL + boff);
                }
                #pragma unroll
                for (int nt = 0; nt < 8; nt++) {
                    MMA_BF16(out[nt], pah[kc], vh[nt]);
                    MMA_BF16(out[nt], pah[kc], vl[nt]);
                    MMA_BF16(out[nt], pal[kc], vh[nt]);
                }
            }
        }

        // ---- pair barrier, then next BD band ----
        asm volatile("bar.sync %0, 64;" :: "r"(1 + mt) : "memory");
        if (kt + 1 < ntiles) {
            float bda[4][4];
            #pragma unroll
            for (int nt = 0; nt < 4; nt++)
                #pragma unroll
                for (int q = 0; q < 4; q++) bda[nt][q] = 0.f;
            GEMM_NK(bda, qvh, qvl, sb + O_RH + buf*TB, sb + O_RL + buf*TB);
            float* bdw = bds + buf * 64 * BDS;
            #pragma unroll
            for (int nt = 0; nt < 4; nt++) {
                int tc = bro + nt*8 + 2*c;
                *reinterpret_cast<float2*>(&bdw[(aro+r)*BDS + tc]) = make_float2(bda[nt][0], bda[nt][1]);
                *reinterpret_cast<float2*>(&bdw[(aro+r+8)*BDS + tc]) = make_float2(bda[nt][2], bda[nt][3]);
            }
        }
    }

    // ---- combine jh halves (REDS even -> aligned float2) ----
    float* red = bds;
    __syncthreads();
    if (jh == 0) {
        #pragma unroll
        for (int nt = 0; nt < 8; nt++) {
            int col = nt*8 + 2*c;
            *reinterpret_cast<float2*>(&red[(aro+r)*REDS + col])   = make_float2(out[nt][0], out[nt][1]);
            *reinterpret_cast<float2*>(&red[(aro+r+8)*REDS + col]) = make_float2(out[nt][2], out[nt][3]);
        }
        if (c == 0) {
            mred[aro+r] = mrun0;   mred[aro+r+8] = mrun1;
            lred[aro+r] = lsum0;   lred[aro+r+8] = lsum1;
        }
    }
    __syncthreads();
    if (jh == 1) {
        float mA0 = mred[aro+r],   lA0 = lred[aro+r];
        float mA1 = mred[aro+r+8], lA1 = lred[aro+r+8];
        float M0 = fmaxf(mA0, mrun0), M1 = fmaxf(mA1, mrun1);
        float eA0 = __expf(mA0 - M0), eB0 = __expf(mrun0 - M0);
        float eA1 = __expf(mA1 - M1), eB1 = __expf(mrun1 - M1);
        float inv0 = 1.f / (lA0*eA0 + lsum0*eB0);
        float inv1 = 1.f / (lA1*eA1 + lsum1*eB1);
        #pragma unroll
        for (int nt = 0; nt < 8; nt++) {
            int col = nt*8 + 2*c;
            float2 oA0 = *reinterpret_cast<float2*>(&red[(aro+r)*REDS + col]);
            float2 oA1 = *reinterpret_cast<float2*>(&red[(aro+r+8)*REDS + col]);
            float v0 = (oA0.x*eA0 + out[nt][0]*eB0) * inv0;
            float v1 = (oA0.y*eA0 + out[nt][1]*eB0) * inv0;
            float v2 = (oA1.x*eA1 + out[nt][2]*eB1) * inv1;
            float v3 = (oA1.y*eA1 + out[nt][3]*eB1) * inv1;
            size_t row0 = (size_t)(b*QLEN + i0 + aro + r) * DM + hh*DH + col;
            size_t row1 = row0 + 8*DM;
            uint32_t h, l;
            split2(v0, v1, h, l);
            *(uint32_t*)&g_avhi[row0] = h; *(uint32_t*)&g_avlo[row0] = l;
            split2(v2, v3, h, l);
            *(uint32_t*)&g_avhi[row1] = h; *(uint32_t*)&g_avlo[row1] = l;
        }
    }
}

// ---------------- launch ----------------
extern "C" void kernel_launch(void* const* d_in, const int* in_sizes, int n_in,
                              void* d_out, int out_size)
{
    (void)in_sizes; (void)n_in; (void)out_size;
    const float* x   = (const float*)d_in[0];
    const float* mem = (const float*)d_in[1];
    const float* pos = (const float*)d_in[2];
    const float* Wq  = (const float*)d_in[4];
    const float* Wk  = (const float*)d_in[5];
    const float* Wv  = (const float*)d_in[6];
    const float* Wr  = (const float*)d_in[7];
    const float* Wo  = (const float*)d_in[8];
    const float* rwb = (const float*)d_in[9];
    const float* rrb = (const float*)d_in[10];
    float* out = (float*)d_out;

    bf16 *pwh, *pwl, *pavh, *pavl;
    cudaGetSymbolAddress((void**)&pwh,  g_whi);
    cudaGetSymbolAddress((void**)&pwl,  g_wlo);
    cudaGetSymbolAddress((void**)&pavh, g_avhi);
    cudaGetSymbolAddress((void**)&pavl, g_avlo);

    prep_split<<<(PREP_TOT + 255)/256, 256>>>(x, pos, Wq, Wk, Wv, Wr, Wo);
    concat_split_kernel<<<(BSZ*KLEN*DM/4 + 255)/256, 256>>>(mem, x);

    cudaFuncSetAttribute(gemm_proj4, cudaFuncAttributeMaxDynamicSharedMemorySize, GEMM_SMEMB);
    gemm_proj4<<<dim3(DM/128, 96), 256, GEMM_SMEMB>>>();

    cudaFuncSetAttribute(attn_mma_kernel, cudaFuncAttributeMaxDynamicSharedMemorySize, ATT_SMEM);
    attn_mma_kernel<<<dim3(QLEN/64, BSZ*NH), 256, ATT_SMEM>>>(rwb, rrb);

    cudaFuncSetAttribute(gemm_bf16, cudaFuncAttributeMaxDynamicSharedMemorySize, GEMM_SMEMB);
    gemm_bf16<<<dim3(DM/128, BSZ*QLEN/128), 256, GEMM_SMEMB>>>(pavh, pavl, pwh+4*DM*DM, pwl+4*DM*DM, out, BSZ*QLEN, DM, DM);
}

// round 9
// speedup vs baseline: 3.1861x; 1.0844x over previous
#include <cuda_runtime.h>
#include <cuda_bf16.h>
#include <cstdint>
#include <math.h>

#define BSZ 2
#define QLEN 1024
#define MLEN 1024
#define KLEN 2048
#define NH 16
#define DH 64
#define DM 1024

typedef __nv_bfloat16 bf16;
typedef __nv_bfloat162 bf162;

// ---------------- scratch ----------------
__device__ float g_q  [BSZ*QLEN*DM];
__device__ bf16 g_khi [BSZ*KLEN*DM];
__device__ bf16 g_klo [BSZ*KLEN*DM];
__device__ bf16 g_vhi [BSZ*KLEN*DM];
__device__ bf16 g_vlo [BSZ*KLEN*DM];
__device__ bf16 g_rhi [KLEN*DM];
__device__ bf16 g_rlo [KLEN*DM];
__device__ bf16 g_xhi [BSZ*QLEN*DM];
__device__ bf16 g_xlo [BSZ*QLEN*DM];
__device__ bf16 g_kihi[BSZ*KLEN*DM];
__device__ bf16 g_kilo[BSZ*KLEN*DM];
__device__ bf16 g_pohi[KLEN*DM];
__device__ bf16 g_polo[KLEN*DM];
__device__ bf16 g_whi [5*DM*DM];
__device__ bf16 g_wlo [5*DM*DM];
__device__ bf16 g_avhi[BSZ*QLEN*DM];
__device__ bf16 g_avlo[BSZ*QLEN*DM];

// ---------------- helpers ----------------
__device__ __forceinline__ uint32_t smem_to_u32(const void* p) {
    uint32_t a;
    asm("{ .reg .u64 t; cvta.to.shared.u64 t, %1; cvt.u32.u64 %0, t; }" : "=r"(a) : "l"(p));
    return a;
}
#define CP_ASYNC16(dst, src) \
    asm volatile("cp.async.cg.shared.global [%0], [%1], 16;" :: "r"(dst), "l"(src) : "memory")
#define CP_COMMIT() asm volatile("cp.async.commit_group;" ::: "memory")
#define CP_WAIT1()  asm volatile("cp.async.wait_group 1;" ::: "memory")
#define CP_WAIT0()  asm volatile("cp.async.wait_group 0;" ::: "memory")

#define MMA_BF16(d, a, b) \
    asm volatile("mma.sync.aligned.m16n8k16.row.col.f32.bf16.bf16.f32 " \
        "{%0,%1,%2,%3}, {%4,%5,%6,%7}, {%8,%9}, {%0,%1,%2,%3};" \
        : "+f"((d)[0]), "+f"((d)[1]), "+f"((d)[2]), "+f"((d)[3]) \
        : "r"((a)[0]), "r"((a)[1]), "r"((a)[2]), "r"((a)[3]), \
          "r"((b)[0]), "r"((b)[1]))

#define LDMX4(r0, r1, r2, r3, addr) \
    asm volatile("ldmatrix.sync.aligned.m8n8.x4.shared.b16 {%0,%1,%2,%3}, [%4];" \
        : "=r"(r0), "=r"(r1), "=r"(r2), "=r"(r3) : "r"(addr))
#define LDMX4T(r0, r1, r2, r3, addr) \
    asm volatile("ldmatrix.sync.aligned.m8n8.x4.trans.shared.b16 {%0,%1,%2,%3}, [%4];" \
        : "=r"(r0), "=r"(r1), "=r"(r2), "=r"(r3) : "r"(addr))

__device__ __forceinline__ void split2(float a, float b, uint32_t& hi, uint32_t& lo) {
    bf162 h = __floats2bfloat162_rn(a, b);
    bf162 l = __floats2bfloat162_rn(a - __bfloat162float(h.x), b - __bfloat162float(h.y));
    hi = *reinterpret_cast<uint32_t*>(&h);
    lo = *reinterpret_cast<uint32_t*>(&l);
}

// ---------------- prep (fused): split x, pos, 5 weights ----------------
#define XN4 (BSZ*QLEN*DM/4)
#define PN4 (KLEN*DM/4)
#define WN4 (DM*DM/4)
#define PREP_TOT (XN4 + PN4 + 5*WN4)

__global__ void prep_split(const float* __restrict__ x, const float* __restrict__ pos,
                           const float* __restrict__ Wq, const float* __restrict__ Wk,
                           const float* __restrict__ Wv, const float* __restrict__ Wr,
                           const float* __restrict__ Wo) {
    int idx = blockIdx.x * blockDim.x + threadIdx.x;
    if (idx >= PREP_TOT) return;
    const float* src; bf16 *hi, *lo; int base;
    if (idx < XN4)                { src = x;  hi = g_xhi; lo = g_xlo; base = 0; }
    else if (idx < XN4+PN4)       { src = pos; hi = g_pohi; lo = g_polo; base = XN4; }
    else if (idx < XN4+PN4+WN4)   { src = Wq; hi = g_whi;        lo = g_wlo;        base = XN4+PN4; }
    else if (idx < XN4+PN4+2*WN4) { src = Wk; hi = g_whi+DM*DM;  lo = g_wlo+DM*DM;  base = XN4+PN4+WN4; }
    else if (idx < XN4+PN4+3*WN4) { src = Wv; hi = g_whi+2*DM*DM; lo = g_wlo+2*DM*DM; base = XN4+PN4+2*WN4; }
    else if (idx < XN4+PN4+4*WN4) { src = Wr; hi = g_whi+3*DM*DM; lo = g_wlo+3*DM*DM; base = XN4+PN4+3*WN4; }
    else                          { src = Wo; hi = g_whi+4*DM*DM; lo = g_wlo+4*DM*DM; base = XN4+PN4+4*WN4; }
    int i = idx - base;
    float4 v = reinterpret_cast<const float4*>(src)[i];
    uint32_t h0, l0, h1, l1;
    split2(v.x, v.y, h0, l0);
    split2(v.z, v.w, h1, l1);
    reinterpret_cast<uint2*>(hi)[i] = make_uint2(h0, h1);
    reinterpret_cast<uint2*>(lo)[i] = make_uint2(l0, l1);
}

__global__ void concat_split_kernel(const float* __restrict__ mem, const float* __restrict__ x) {
    int idx = blockIdx.x * blockDim.x + threadIdx.x;
    if (idx >= BSZ*KLEN*DM/4) return;
    int e4   = idx & (DM/4 - 1);
    int rest = idx / (DM/4);
    int j = rest & (KLEN - 1);
    int b = rest >> 11;
    float4 v;
    if (j < MLEN) v = reinterpret_cast<const float4*>(mem)[(b*MLEN + j)*(DM/4) + e4];
    else          v = reinterpret_cast<const float4*>(x)[(b*QLEN + (j - MLEN))*(DM/4) + e4];
    uint32_t h0, l0, h1, l1;
    split2(v.x, v.y, h0, l0);
    split2(v.z, v.w, h1, l1);
    reinterpret_cast<uint2*>(g_kihi)[idx] = make_uint2(h0, h1);
    reinterpret_cast<uint2*>(g_kilo)[idx] = make_uint2(l0, l1);
}

// ================= bf16 2-split GEMM body (2-stage, 2 CTAs/SM) =================
#define GBK 32
#define ROWB 40
#define TILEB (128*ROWB)
#define STGB (4*TILEB)
#define GEMM_SMEMB (2*STGB*2)

__device__ __forceinline__ void gemm_body(
    const bf16* __restrict__ Ahi, const bf16* __restrict__ Alo,
    const bf16* __restrict__ Bhi, const bf16* __restrict__ Blo,
    float* __restrict__ C, bf16* __restrict__ Chi, bf16* __restrict__ Clo,
    int m0, int n0, int N, int K)
{
    extern __shared__ bf16 sb[];
    const int tid = threadIdx.x;
    const int wid = tid >> 5, lane = tid & 31;
    const int wm = (wid >> 2) * 64, wn = (wid & 3) * 32;
    const int r = lane >> 2, c = lane & 3;
    const uint32_t sbase = smem_to_u32(sb);

    float acc[4][4][4];
    #pragma unroll
    for (int i = 0; i < 4; i++)
        #pragma unroll
        for (int j = 0; j < 4; j++)
            #pragma unroll
            for (int q = 0; q < 4; q++) acc[i][j][q] = 0.f;

    const bf16* mats[4] = { Ahi + (size_t)m0*K, Alo + (size_t)m0*K,
                            Bhi + (size_t)n0*K, Blo + (size_t)n0*K };
    int l_mat[8], l_row[8], l_ch[8];
    #pragma unroll
    for (int i = 0; i < 8; i++) {
        int id = i*256 + tid;
        l_mat[i] = id >> 9; l_row[i] = (id >> 2) & 127; l_ch[i] = id & 3;
    }

    #define G_ISSUE(kt) do { \
        int _s = (kt) & 1, _k0 = (kt) * GBK; \
        _Pragma("unroll") \
        for (int _i = 0; _i < 8; _i++) { \
            const bf16* _src = mats[l_mat[_i]] + (size_t)l_row[_i]*K + _k0 + l_ch[_i]*8; \
            uint32_t _dst = sbase + (uint32_t)(_s*STGB + l_mat[_i]*TILEB + l_row[_i]*ROWB + l_ch[_i]*8)*2; \
            CP_ASYNC16(_dst, _src); \
        } \
    } while (0)

    const int nK = K / GBK;
    G_ISSUE(0); CP_COMMIT();

    const int aRow = lane & 15, aColOff = (lane >> 4) << 3;
    const int bRow = lane & 7, bColOff = ((lane >> 3) & 1) << 3, bBlk = lane >> 4;

    for (int kt = 0; kt < nK; kt++) {
        if (kt + 1 < nK) { G_ISSUE(kt + 1); CP_COMMIT(); CP_WAIT1(); }
        else             { CP_WAIT0(); }
        __syncthreads();

        uint32_t Sb = sbase + (uint32_t)((kt & 1) * STGB) * 2;
        uint32_t Ah = Sb, Al = Sb + TILEB*2, Bh = Sb + 2*TILEB*2, Bl = Sb + 3*TILEB*2;

        #pragma unroll
        for (int k16 = 0; k16 < GBK; k16 += 16) {
            uint32_t ah[4][4], al[4][4], bh[4][2], bl[4][2];
            #pragma unroll
            for (int mt = 0; mt < 4; mt++) {
                uint32_t off = (uint32_t)((wm + mt*16 + aRow)*ROWB + k16 + aColOff) * 2;
                LDMX4(ah[mt][0], ah[mt][1], ah[mt][2], ah[mt][3], Ah + off);
                LDMX4(al[mt][0], al[mt][1], al[mt][2], al[mt][3], Al + off);
            }
            #pragma unroll
            for (int p = 0; p < 2; p++) {
                uint32_t off = (uint32_t)((wn + (2*p + bBlk)*8 + bRow)*ROWB + k16 + bColOff) * 2;
                LDMX4(bh[2*p][0], bh[2*p][1], bh[2*p+1][0], bh[2*p+1][1], Bh + off);
                LDMX4(bl[2*p][0], bl[2*p][1], bl[2*p+1][0], bl[2*p+1][1], Bl + off);
            }
            #pragma unroll
            for (int mt = 0; mt < 4; mt++)
                #pragma unroll
                for (int nt = 0; nt < 4; nt++) {
                    MMA_BF16(acc[mt][nt], ah[mt], bh[nt]);
                    MMA_BF16(acc[mt][nt], ah[mt], bl[nt]);
                    MMA_BF16(acc[mt][nt], al[mt], bh[nt]);
                }
        }
        __syncthreads();
    }
    if (Chi) {
        #pragma unroll
        for (int mt = 0; mt < 4; mt++) {
            int row = m0 + wm + mt*16 + r;
            #pragma unroll
            for (int nt = 0; nt < 4; nt++) {
                int col = n0 + wn + nt*8 + 2*c;
                uint32_t h, l;
                split2(acc[mt][nt][0], acc[mt][nt][1], h, l);
                *(uint32_t*)&Chi[(size_t)row*N + col] = h;
                *(uint32_t*)&Clo[(size_t)row*N + col] = l;
                split2(acc[mt][nt][2], acc[mt][nt][3], h, l);
                *(uint32_t*)&Chi[(size_t)(row+8)*N + col] = h;
                *(uint32_t*)&Clo[(size_t)(row+8)*N + col] = l;
            }
        }
    } else {
        #pragma unroll
        for (int mt = 0; mt < 4; mt++) {
            int row = m0 + wm + mt*16 + r;
            #pragma unroll
            for (int nt = 0; nt < 4; nt++) {
                int col = n0 + wn + nt*8 + 2*c;
                *reinterpret_cast<float2*>(&C[(size_t)row*N + col]) = make_float2(acc[mt][nt][0], acc[mt][nt][1]);
                *reinterpret_cast<float2*>(&C[(size_t)(row+8)*N + col]) = make_float2(acc[mt][nt][2], acc[mt][nt][3]);
            }
        }
    }
}

// fused projection GEMMs: q | k | v | r (grid.y = 16+32+32+16)
__global__ __launch_bounds__(256, 2) void gemm_proj4() {
    int y = blockIdx.y;
    const int WN = DM*DM;
    if (y < 16)
        gemm_body(g_xhi, g_xlo, g_whi, g_wlo, g_q, nullptr, nullptr, y*128, blockIdx.x*128, DM, DM);
    else if (y < 48)
        gemm_body(g_kihi, g_kilo, g_whi+WN, g_wlo+WN, nullptr, g_khi, g_klo, (y-16)*128, blockIdx.x*128, DM, DM);
    else if (y < 80)
        gemm_body(g_kihi, g_kilo, g_whi+2*WN, g_wlo+2*WN, nullptr, g_vhi, g_vlo, (y-48)*128, blockIdx.x*128, DM, DM);
    else
        gemm_body(g_pohi, g_polo, g_whi+3*WN, g_wlo+3*WN, nullptr, g_rhi, g_rlo, (y-80)*128, blockIdx.x*128, DM, DM);
}

__global__ __launch_bounds__(256, 2) void gemm_bf16(
    const bf16* __restrict__ Ahi, const bf16* __restrict__ Alo,
    const bf16* __restrict__ Bhi, const bf16* __restrict__ Blo,
    float* __restrict__ C, int M, int N, int K)
{
    gemm_body(Ahi, Alo, Bhi, Blo, C, nullptr, nullptr, blockIdx.y*128, blockIdx.x*128, N, K);
}

// ================= tensor-core flash attention (P in registers) =================
#define ST 72
#define TB 9216
#define O_QU 0
#define O_KH (4*TB)
#define O_KL (6*TB)
#define O_VH (8*TB)
#define O_VL (10*TB)
#define O_RH (12*TB)
#define O_RL (14*TB)
#define O_BD (16*TB)
#define BDS 66
#define O_ST (O_BD + 2*64*BDS*4)
#define ATT_SMEM (O_ST + 1024)
#define REDS 66

__global__ __launch_bounds__(256, 1) void attn_mma_kernel(
    const float* __restrict__ r_w_bias, const float* __restrict__ r_r_bias)
{
    extern __shared__ char smc[];
    const uint32_t sb = smem_to_u32(smc);
    float* bds  = (float*)(smc + O_BD);
    float* mred = (float*)(smc + O_ST);
    float* lred = mred + 64;

    const int tid = threadIdx.x;
    const int w = tid >> 5, lane = tid & 31;
    const int mt = w & 3, jh = w >> 2;
    const int r = lane >> 2, c = lane & 3;
    const int i0 = (15 - (int)blockIdx.x) * 64;
    const int b = blockIdx.y >> 4, hh = blockIdx.y & 15;
    const int lrow = tid >> 2;
    const int dseg = (tid & 3) * 16;
    const int aro = mt*16, bro = jh*32;
    const int relbase0 = 960 - i0;
    const int ntiles = i0/64 + 17;
    const size_t headoff = (size_t)hh*DH;

    const int aRow = lane & 15, aColOff = (lane >> 4) << 3;
    const int bRow = lane & 7, bHalf = (lane >> 3) & 1, bBlk = lane >> 4;

    #define CP_TILE(dstoff, gptr) do { \
        uint32_t _d = sb + (uint32_t)(dstoff) + (uint32_t)(lrow*ST + dseg)*2; \
        const bf16* _s = (gptr) + dseg; \
        CP_ASYNC16(_d, _s); CP_ASYNC16(_d + 16, _s + 8); \
    } while (0)
    #define ISSUE_KV(kt, bufi) do { \
        size_t _row = (size_t)(b*KLEN + (kt)*64 + lrow)*DM + headoff; \
        CP_TILE(O_KH + (bufi)*TB, g_khi + _row); \
        CP_TILE(O_KL + (bufi)*TB, g_klo + _row); \
        CP_TILE(O_VH + (bufi)*TB, g_vhi + _row); \
        CP_TILE(O_VL + (bufi)*TB, g_vlo + _row); \
    } while (0)
    #define ISSUE_RB(band, bufi) do { \
        int _rel = relbase0 + (band)*64 + lrow; \
        _rel = _rel < 0 ? 0 : (_rel > KLEN-1 ? KLEN-1 : _rel); \
        size_t _row = (size_t)_rel*DM + headoff; \
        CP_TILE(O_RH + (bufi)*TB, g_rhi + _row); \
        CP_TILE(O_RL + (bufi)*TB, g_rlo + _row); \
    } while (0)

    ISSUE_RB(0, 0); CP_COMMIT();
    ISSUE_RB(1, 1); ISSUE_KV(0, 0); CP_COMMIT();

    // ---- q prep into smem ----
    {
        const float* qrow = g_q + ((size_t)(b*QLEN + i0 + lrow))*DM + headoff + dseg;
        const float* ub = r_w_bias + headoff + dseg;
        const float* vb = r_r_bias + headoff + dseg;
        bf16* quhi = (bf16*)(smc + O_QU);
        bf16* qulo = (bf16*)(smc + O_QU + TB);
        bf16* qvhi = (bf16*)(smc + O_QU + 2*TB);
        bf16* qvlo = (bf16*)(smc + O_QU + 3*TB);
        #pragma unroll
        for (int p = 0; p < 4; p++) {
            float4 q4 = reinterpret_cast<const float4*>(qrow)[p];
            float4 u4 = reinterpret_cast<const float4*>(ub)[p];
            float4 v4 = reinterpret_cast<const float4*>(vb)[p];
            int dd = dseg + p*4;
            uint32_t h, l;
            split2((q4.x+u4.x)*0.125f, (q4.y+u4.y)*0.125f, h, l);
            *(uint32_t*)&quhi[lrow*ST+dd] = h; *(uint32_t*)&qulo[lrow*ST+dd] = l;
            split2((q4.z+u4.z)*0.125f, (q4.w+u4.w)*0.125f, h, l);
            *(uint32_t*)&quhi[lrow*ST+dd+2] = h; *(uint32_t*)&qulo[lrow*ST+dd+2] = l;
            split2((q4.x+v4.x)*0.125f, (q4.y+v4.y)*0.125f, h, l);
            *(uint32_t*)&qvhi[lrow*ST+dd] = h; *(uint32_t*)&qvlo[lrow*ST+dd] = l;
            split2((q4.z+v4.z)*0.125f, (q4.w+v4.w)*0.125f, h, l);
            *(uint32_t*)&qvhi[lrow*ST+dd+2] = h; *(uint32_t*)&qvlo[lrow*ST+dd+2] = l;
        }
    }
    CP_WAIT1();            // rb0 ready
    __syncthreads();       // + q stores visible

    // ---- preload q fragments ----
    uint32_t quh[4][4], qul[4][4], qvh[4][4], qvl[4][4];
    #pragma unroll
    for (int kc = 0; kc < 4; kc++) {
        uint32_t aoff = (uint32_t)((aro + aRow)*ST + kc*16 + aColOff) * 2;
        LDMX4(quh[kc][0], quh[kc][1], quh[kc][2], quh[kc][3], sb + O_QU + aoff);
        LDMX4(qul[kc][0], qul[kc][1], qul[kc][2], qul[kc][3], sb + O_QU + TB + aoff);
        LDMX4(qvh[kc][0], qvh[kc][1], qvh[kc][2], qvh[kc][3], sb + O_QU + 2*TB + aoff);
        LDMX4(qvl[kc][0], qvl[kc][1], qvl[kc][2], qvl[kc][3], sb + O_QU + 3*TB + aoff);
    }

    // fragment loader for B row-major [n][k]
    #define LOADB_NK(BH, BL, kcv, BHbase, BLbase) do { \
        _Pragma("unroll") \
        for (int p = 0; p < 2; p++) { \
            uint32_t boff = (uint32_t)((bro + (2*p + bBlk)*8 + bRow)*ST + (kcv)*16 + bHalf*8) * 2; \
            LDMX4(BH[2*p][0], BH[2*p][1], BH[2*p+1][0], BH[2*p+1][1], (BHbase) + boff); \
            LDMX4(BL[2*p][0], BL[2*p][1], BL[2*p+1][0], BL[2*p+1][1], (BLbase) + boff); \
        } \
    } while (0)

    // 64x32 GEMM, software-pipelined fragment loads
    #define GEMM_NK(ACC, AH, AL, BHbase, BLbase) do { \
        uint32_t bhf[2][4][2], blf[2][4][2]; \
        LOADB_NK(bhf[0], blf[0], 0, BHbase, BLbase); \
        _Pragma("unroll") \
        for (int kc = 0; kc < 4; kc++) { \
            int cur = kc & 1; \
            if (kc < 3) LOADB_NK(bhf[cur^1], blf[cur^1], kc+1, BHbase, BLbase); \
            _Pragma("unroll") \
            for (int nt = 0; nt < 4; nt++) { \
                MMA_BF16(ACC[nt], AH[kc], bhf[cur][nt]); \
                MMA_BF16(ACC[nt], AH[kc], blf[cur][nt]); \
                MMA_BF16(ACC[nt], AL[kc], bhf[cur][nt]); \
            } \
        } \
    } while (0)

    #define BD_STORE(bda, bufidx) do { \
        float* bdw = bds + (bufidx) * 64 * BDS; \
        _Pragma("unroll") \
        for (int nt = 0; nt < 4; nt++) { \
            int tc = bro + nt*8 + 2*c; \
            *reinterpret_cast<float2*>(&bdw[(aro+r)*BDS + tc]) = make_float2(bda[nt][0], bda[nt][1]); \
            *reinterpret_cast<float2*>(&bdw[(aro+r+8)*BDS + tc]) = make_float2(bda[nt][2], bda[nt][3]); \
        } \
    } while (0)

    // ---- prologue BD bands 0,1 ----
    {
        float bda[4][4];
        #pragma unroll
        for (int nt = 0; nt < 4; nt++)
            #pragma unroll
            for (int q = 0; q < 4; q++) bda[nt][q] = 0.f;
        GEMM_NK(bda, qvh, qvl, sb + O_RH, sb + O_RL);
        BD_STORE(bda, 0);
    }
    __syncthreads();                 // rbuf0 free
    ISSUE_RB(2, 0); CP_COMMIT();
    CP_WAIT1();                      // rb1 + kv0 ready
    __syncthreads();
    {
        float bda[4][4];
        #pragma unroll
        for (int nt = 0; nt < 4; nt++)
            #pragma unroll
            for (int q = 0; q < 4; q++) bda[nt][q] = 0.f;
        GEMM_NK(bda, qvh, qvl, sb + O_RH + TB, sb + O_RL + TB);
        BD_STORE(bda, 1);
    }

    float out[8][4];
    #pragma unroll
    for (int nt = 0; nt < 8; nt++)
        #pragma unroll
        for (int q = 0; q < 4; q++) out[nt][q] = 0.f;
    float lsum0 = 0.f, lsum1 = 0.f, mrun0 = -1e4f, mrun1 = -1e4f;

    for (int kt = 0; kt < ntiles; kt++) {
        const int j0 = kt * 64;
        const int buf = kt & 1, nbuf = buf ^ 1;
        CP_WAIT0();
        __syncthreads();
        if (kt + 1 < ntiles) {
            ISSUE_KV(kt + 1, nbuf);
            ISSUE_RB(kt + 3, nbuf);
            CP_COMMIT();
        }

        // ---- AC ----
        float s[4][4];
        #pragma unroll
        for (int nt = 0; nt < 4; nt++)
            #pragma unroll
            for (int q = 0; q < 4; q++) s[nt][q] = 0.f;
        GEMM_NK(s, quh, qul, sb + O_KH + buf*TB, sb + O_KL + buf*TB);

        // ---- BD gather + mask ----
        const float* bdLo = bds + buf * 64 * BDS;
        const float* bdHi = bds + nbuf * 64 * BDS;
        #pragma unroll
        for (int nt = 0; nt < 4; nt++)
            #pragma unroll
            for (int q = 0; q < 4; q++) {
                int il = aro + r + ((q >= 2) ? 8 : 0);
                int jl = bro + nt*8 + 2*c + (q & 1);
                int t = jl - il + 63;
                float bd = (t < 64) ? bdLo[il*BDS + t] : bdHi[il*BDS + t - 64];
                float sc = s[nt][q] + bd;
                if (j0 + jl > i0 + il + MLEN) sc = -1e30f;
                s[nt][q] = sc;
            }

        // ---- pair barrier + next BD band (tensor work overlaps others' softmax) ----
        if (kt + 1 < ntiles) {
            asm volatile("bar.sync %0, 64;" :: "r"(1 + mt) : "memory");
            float bda[4][4];
            #pragma unroll
            for (int nt = 0; nt < 4; nt++)
                #pragma unroll
                for (int q = 0; q < 4; q++) bda[nt][q] = 0.f;
            GEMM_NK(bda, qvh, qvl, sb + O_RH + buf*TB, sb + O_RL + buf*TB);
            BD_STORE(bda, buf);
        }

        // ---- per-half online softmax ----
        float pmax0 = -1e30f, pmax1 = -1e30f;
        #pragma unroll
        for (int nt = 0; nt < 4; nt++) {
            pmax0 = fmaxf(pmax0, fmaxf(s[nt][0], s[nt][1]));
            pmax1 = fmaxf(pmax1, fmaxf(s[nt][2], s[nt][3]));
        }
        pmax0 = fmaxf(pmax0, __shfl_xor_sync(~0u, pmax0, 1));
        pmax0 = fmaxf(pmax0, __shfl_xor_sync(~0u, pmax0, 2));
        pmax1 = fmaxf(pmax1, __shfl_xor_sync(~0u, pmax1, 1));
        pmax1 = fmaxf(pmax1, __shfl_xor_sync(~0u, pmax1, 2));
        float mn0 = fmaxf(mrun0, pmax0), mn1 = fmaxf(mrun1, pmax1);
        float ps0 = 0.f, ps1 = 0.f;
        #pragma unroll
        for (int nt = 0; nt < 4; nt++) {
            s[nt][0] = __expf(s[nt][0] - mn0);
            s[nt][1] = __expf(s[nt][1] - mn0);
            s[nt][2] = __expf(s[nt][2] - mn1);
            s[nt][3] = __expf(s[nt][3] - mn1);
            ps0 += s[nt][0] + s[nt][1];
            ps1 += s[nt][2] + s[nt][3];
        }
        ps0 += __shfl_xor_sync(~0u, ps0, 1); ps0 += __shfl_xor_sync(~0u, ps0, 2);
        ps1 += __shfl_xor_sync(~0u, ps1, 1); ps1 += __shfl_xor_sync(~0u, ps1, 2);
        float corr0 = __expf(mrun0 - mn0), corr1 = __expf(mrun1 - mn1);
        lsum0 = lsum0 * corr0 + ps0;
        lsum1 = lsum1 * corr1 + ps1;
        mrun0 = mn0; mrun1 = mn1;
        #pragma unroll
        for (int nt = 0; nt < 8; nt++) {
            out[nt][0] *= corr0; out[nt][1] *= corr0;
            out[nt][2] *= corr1; out[nt][3] *= corr1;
        }

        // ---- pack P A-frags from registers ----
        uint32_t pah[2][4], pal[2][4];
        #pragma unroll
        for (int kc = 0; kc < 2; kc++) {
            split2(s[2*kc][0],   s[2*kc][1],   pah[kc][0], pal[kc][0]);
            split2(s[2*kc][2],   s[2*kc][3],   pah[kc][1], pal[kc][1]);
            split2(s[2*kc+1][0], s[2*kc+1][1], pah[kc][2], pal[kc][2]);
            split2(s[2*kc+1][2], s[2*kc+1][3], pah[kc][3], pal[kc][3]);
        }

        // ---- PV: out += P(16 x 32own) @ V(32own x 64), pipelined V frags ----
        {
            uint32_t VH = sb + O_VH + buf*TB, VL = sb + O_VL + buf*TB;
            uint32_t vhf[2][8][2], vlf[2][8][2];
            #define LOADV(slot, kcv) do { \
                int co = jh*32 + (kcv)*16; \
                _Pragma("unroll") \
                for (int p = 0; p < 4; p++) { \
                    uint32_t boff = (uint32_t)((co + bRow + bHalf*8)*ST + (2*p + bBlk)*8) * 2; \
                    LDMX4T(vhf[slot][2*p][0], vhf[slot][2*p][1], vhf[slot][2*p+1][0], vhf[slot][2*p+1][1], VH + boff); \
                    LDMX4T(vlf[slot][2*p][0], vlf[slot][2*p][1], vlf[slot][2*p+1][0], vlf[slot][2*p+1][1], VL + boff); \
                } \
            } while (0)
            LOADV(0, 0);
            #pragma unroll
            for (int kc = 0; kc < 2; kc++) {
                if (kc == 0) LOADV(1, 1);
                #pragma unroll
                for (int nt = 0; nt < 8; nt++) {
                    MMA_BF16(out[nt], pah[kc], vhf[kc][nt]);
                    MMA_BF16(out[nt], pah[kc], vlf[kc][nt]);
                    MMA_BF16(out[nt], pal[kc], vhf[kc][nt]);
                }
            }
            #undef LOADV
        }
    }

    // ---- combine jh halves ----
    float* red = bds;
    __syncthreads();
    if (jh == 0) {
        #pragma unroll
        for (int nt = 0; nt < 8; nt++) {
            int col = nt*8 + 2*c;
            *reinterpret_cast<float2*>(&red[(aro+r)*REDS + col])   = make_float2(out[nt][0], out[nt][1]);
            *reinterpret_cast<float2*>(&red[(aro+r+8)*REDS + col]) = make_float2(out[nt][2], out[nt][3]);
        }
        if (c == 0) {
            mred[aro+r] = mrun0;   mred[aro+r+8] = mrun1;
            lred[aro+r] = lsum0;   lred[aro+r+8] = lsum1;
        }
    }
    __syncthreads();
    if (jh == 1) {
        float mA0 = mred[aro+r],   lA0 = lred[aro+r];
        float mA1 = mred[aro+r+8], lA1 = lred[aro+r+8];
        float M0 = fmaxf(mA0, mrun0), M1 = fmaxf(mA1, mrun1);
        float eA0 = __expf(mA0 - M0), eB0 = __expf(mrun0 - M0);
        float eA1 = __expf(mA1 - M1), eB1 = __expf(mrun1 - M1);
        float inv0 = 1.f / (lA0*eA0 + lsum0*eB0);
        float inv1 = 1.f / (lA1*eA1 + lsum1*eB1);
        #pragma unroll
        for (int nt = 0; nt < 8; nt++) {
            int col = nt*8 + 2*c;
            float2 oA0 = *reinterpret_cast<float2*>(&red[(aro+r)*REDS + col]);
            float2 oA1 = *reinterpret_cast<float2*>(&red[(aro+r+8)*REDS + col]);
            float v0 = (oA0.x*eA0 + out[nt][0]*eB0) * inv0;
            float v1 = (oA0.y*eA0 + out[nt][1]*eB0) * inv0;
            float v2 = (oA1.x*eA1 + out[nt][2]*eB1) * inv1;
            float v3 = (oA1.y*eA1 + out[nt][3]*eB1) * inv1;
            size_t row0 = (size_t)(b*QLEN + i0 + aro + r) * DM + hh*DH + col;
            size_t row1 = row0 + 8*DM;
            uint32_t h, l;
            split2(v0, v1, h, l);
            *(uint32_t*)&g_avhi[row0] = h; *(uint32_t*)&g_avlo[row0] = l;
            split2(v2, v3, h, l);
            *(uint32_t*)&g_avhi[row1] = h; *(uint32_t*)&g_avlo[row1] = l;
        }
    }
}

// ---------------- launch ----------------
extern "C" void kernel_launch(void* const* d_in, const int* in_sizes, int n_in,
                              void* d_out, int out_size)
{
    (void)in_sizes; (void)n_in; (void)out_size;
    const float* x   = (const float*)d_in[0];
    const float* mem = (const float*)d_in[1];
    const float* pos = (const float*)d_in[2];
    const float* Wq  = (const float*)d_in[4];
    const float* Wk  = (const float*)d_in[5];
    const float* Wv  = (const float*)d_in[6];
    const float* Wr  = (const float*)d_in[7];
    const float* Wo  = (const float*)d_in[8];
    const float* rwb = (const float*)d_in[9];
    const float* rrb = (const float*)d_in[10];
    float* out = (float*)d_out;

    bf16 *pwh, *pwl, *pavh, *pavl;
    cudaGetSymbolAddress((void**)&pwh,  g_whi);
    cudaGetSymbolAddress((void**)&pwl,  g_wlo);
    cudaGetSymbolAddress((void**)&pavh, g_avhi);
    cudaGetSymbolAddress((void**)&pavl, g_avlo);

    prep_split<<<(PREP_TOT + 255)/256, 256>>>(x, pos, Wq, Wk, Wv, Wr, Wo);
    concat_split_kernel<<<(BSZ*KLEN*DM/4 + 255)/256, 256>>>(mem, x);

    cudaFuncSetAttribute(gemm_proj4, cudaFuncAttributeMaxDynamicSharedMemorySize, GEMM_SMEMB);
    gemm_proj4<<<dim3(DM/128, 96), 256, GEMM_SMEMB>>>();

    cudaFuncSetAttribute(attn_mma_kernel, cudaFuncAttributeMaxDynamicSharedMemorySize, ATT_SMEM);
    attn_mma_kernel<<<dim3(QLEN/64, BSZ*NH), 256, ATT_SMEM>>>(rwb, rrb);

    cudaFuncSetAttribute(gemm_bf16, cudaFuncAttributeMaxDynamicSharedMemorySize, GEMM_SMEMB);
    gemm_bf16<<<dim3(DM/128, BSZ*QLEN/128), 256, GEMM_SMEMB>>>(pavh, pavl, pwh+4*DM*DM, pwl+4*DM*DM, out, BSZ*QLEN, DM, DM);
}